// round 14
// baseline (speedup 1.0000x reference)
#include <cuda_runtime.h>
#include <cuda_fp16.h>
#include <math.h>

#define NN 12288
#define SS 4096
#define MM 16384
#define EE 393216
#define FF 256
#define CC 128
#define SLOPE 0.2f
#define HOFF 33554432   // 4096*8192, h output starts here

// ---------------- scratch (static device memory; no allocation) ----------------
__device__ float    g_h  [NN*FF];
__device__ float    g_h2 [NN*FF];
__device__ __half   g_xl [3][NN*FF];    // fp16 rows for gather (layer1: scaled x1024)
__device__ __half   g_m  [3][MM*FF];    // fp16 rows for gather (layer1: scaled x1024)
__device__ float    g_w1 [2][3][FF];
__device__ float    g_w2 [2][3][FF];
__device__ float    g_s1 [3][NN];
__device__ float    g_s2 [2][3][MM];
__device__ float4   g_ninfo[3][NN];     // (s1, max, 1/sum, 1/D)
__device__ float    g_Dv [3][NN];
__device__ int      g_noff[3][NN+1];
__device__ int      g_eoff[3][MM+1];
__device__ int      g_ncur[3][NN];
__device__ int      g_ecur[3][MM];
__device__ int      g_eiN [3][EE];
__device__ int      g_niE [3][EE];
__device__ __half   g_newgh[2][SS*CC];
__device__ __half   g_xsh  [2][SS*CC];
__device__ unsigned g_Wp [4][3][32768];
__device__ unsigned g_Wpc[2][2][16384];

__device__ __forceinline__ float lk(float v){ return v >= 0.f ? v : SLOPE * v; }
__device__ __forceinline__ unsigned packh2(float x, float y){
    __half2 h = __floats2half2_rn(x, y);
    return *(unsigned*)&h;
}

// ---------------- weight prep: fp32 -> packed half2 [K/2][N] ----------------
__global__ void k_prepw(const float* __restrict__ W0, const float* __restrict__ Wh1,
                        const float* __restrict__ W1, const float* __restrict__ Wh2,
                        const float* __restrict__ Wg, const float* __restrict__ Wx){
    int i = blockIdx.x * blockDim.x + threadIdx.x;
    if (i < 4*3*32768){
        int set = i / 98304;
        int r   = i % 98304;
        int z   = r / 32768;
        int off = r % 32768;
        int k2  = off >> 8, n = off & 255;
        const float* W = (set==0)?W0:(set==1)?Wh1:(set==2)?W1:Wh2;
        const float* s = W + (size_t)z*65536 + (size_t)(2*k2)*256 + n;
        g_Wp[set][z][off] = packh2(s[0], s[256]);
    } else {
        int j = i - 4*3*32768;
        if (j < 2*2*16384){
            int set = j / 32768;
            int r   = j % 32768;
            int z   = r / 16384;
            int off = r % 16384;
            int k2  = off >> 7, n = off & 127;
            const float* W = set ? Wx : Wg;
            const float* s = W + (size_t)(z+1)*32768 + (size_t)(2*k2)*128 + n;
            g_Wpc[set][z][off] = packh2(s[0], s[128]);
        }
    }
}

// ---------------- setup: counting-sort CSR build ----------------
__global__ void k_zero(){
    int i = blockIdx.x * blockDim.x + threadIdx.x;
    if (i < 3*(NN+1)) ((int*)g_noff)[i] = 0;
    if (i < 3*(MM+1)) ((int*)g_eoff)[i] = 0;
}

__global__ void k_hist(const int* __restrict__ ni0, const int* __restrict__ ei0,
                       const int* __restrict__ ni1, const int* __restrict__ ei1,
                       const int* __restrict__ ni2, const int* __restrict__ ei2){
    int idx = blockIdx.x * blockDim.x + threadIdx.x;
    if (idx >= 3*EE) return;
    int b = idx / EE, j = idx % EE;
    const int* ni = (b==0) ? ni0 : (b==1) ? ni1 : ni2;
    const int* ei = (b==0) ? ei0 : (b==1) ? ei1 : ei2;
    atomicAdd(&g_noff[b][ni[j]+1], 1);
    atomicAdd(&g_eoff[b][ei[j]+1], 1);
}

__global__ void k_scan(){
    int bid = blockIdx.x;
    int *arr, *cur; int len;
    if (bid < 3){ arr = g_noff[bid];   cur = g_ncur[bid];   len = NN+1; }
    else        { arr = g_eoff[bid-3]; cur = g_ecur[bid-3]; len = MM+1; }
    __shared__ int wsum[32];
    int lane = threadIdx.x & 31, wid = threadIdx.x >> 5;
    int carry = 0;
    for (int base = 0; base < len; base += 1024){
        int i = base + threadIdx.x;
        int v = (i < len) ? arr[i] : 0;
        int s = v;
        #pragma unroll
        for (int o = 1; o < 32; o <<= 1){
            int t = __shfl_up_sync(0xffffffffu, s, o);
            if (lane >= o) s += t;
        }
        if (lane == 31) wsum[wid] = s;
        __syncthreads();
        if (wid == 0){
            int ws = wsum[lane];
            #pragma unroll
            for (int o = 1; o < 32; o <<= 1){
                int t = __shfl_up_sync(0xffffffffu, ws, o);
                if (lane >= o) ws += t;
            }
            wsum[lane] = ws;
        }
        __syncthreads();
        int incl = s + (wid ? wsum[wid-1] : 0) + carry;
        int tot = wsum[31];
        if (i < len){ arr[i] = incl; if (i < len-1) cur[i] = incl; }
        __syncthreads();
        carry += tot;
    }
}

__global__ void k_scatter(const int* __restrict__ ni0, const int* __restrict__ ei0,
                          const int* __restrict__ ni1, const int* __restrict__ ei1,
                          const int* __restrict__ ni2, const int* __restrict__ ei2){
    int idx = blockIdx.x * blockDim.x + threadIdx.x;
    if (idx >= 3*EE) return;
    int b = idx / EE, j = idx % EE;
    const int* ni = (b==0) ? ni0 : (b==1) ? ni1 : ni2;
    const int* ei = (b==0) ? ei0 : (b==1) ? ei1 : ei2;
    int n = ni[j], e = ei[j];
    int pn = atomicAdd(&g_ncur[b][n], 1); g_eiN[b][pn] = e;
    int pe = atomicAdd(&g_ecur[b][e], 1); g_niE[b][pe] = n;
}

// ---------------- fp16 tensor-core GEMM (NN), packed-fp16 B, reg double-buffered ----------------
template<int OUTH>
__global__ void __launch_bounds__(256) k_hmma(
    const float* __restrict__ A, const unsigned* __restrict__ Bp,
    void* __restrict__ Cv, const float* __restrict__ bias,
    int M, int N, int K, int ldc,
    long long sAz, long long sBz, long long sCz, long long sbz,
    int act, float ascale, float inv_ascale, float oscale)
{
    __shared__ unsigned As2[16][136];
    __shared__ unsigned Bs2[16][136];
    int z = blockIdx.z;
    A += (size_t)z * sAz; Bp += (size_t)z * sBz;
    if (bias) bias += (size_t)z * sbz;
    int bm = blockIdx.y * 128, bn = blockIdx.x * 128;
    int tid = threadIdx.x;
    int warp = tid >> 5, lane = tid & 31;
    int wm = warp & 3, wn = warp >> 2;
    int g = lane >> 2, tg = lane & 3;

    float c[2][8][4];
    #pragma unroll
    for (int mt = 0; mt < 2; mt++)
        #pragma unroll
        for (int nt = 0; nt < 8; nt++)
            #pragma unroll
            for (int i = 0; i < 4; i++) c[mt][nt][i] = 0.f;

    float4 va[4]; uint4 vb[2];
    #pragma unroll
    for (int i = 0; i < 4; i++){
        int q = tid + 256*i;
        int r = q >> 3, cc = (q & 7) << 2;
        va[i] = *(const float4*)(A + (size_t)(bm + r) * K + cc);
    }
    #pragma unroll
    for (int i = 0; i < 2; i++){
        int q = tid + 256*i;
        int row = q >> 5, c4 = q & 31;
        vb[i] = *(const uint4*)(Bp + (size_t)row * N + bn + c4*4);
    }

    for (int kt = 0; kt < K; kt += 32){
        #pragma unroll
        for (int i = 0; i < 4; i++){
            int q = tid + 256*i;
            int r = q >> 3, cc = (q & 7) << 2;
            As2[(cc>>1)  ][r] = packh2(va[i].x*ascale, va[i].y*ascale);
            As2[(cc>>1)+1][r] = packh2(va[i].z*ascale, va[i].w*ascale);
        }
        #pragma unroll
        for (int i = 0; i < 2; i++){
            int q = tid + 256*i;
            int row = q >> 5, c4 = q & 31;
            *(uint4*)&Bs2[row][c4*4] = vb[i];
        }
        __syncthreads();
        if (kt + 32 < K){
            #pragma unroll
            for (int i = 0; i < 4; i++){
                int q = tid + 256*i;
                int r = q >> 3, cc = (q & 7) << 2;
                va[i] = *(const float4*)(A + (size_t)(bm + r) * K + kt + 32 + cc);
            }
            #pragma unroll
            for (int i = 0; i < 2; i++){
                int q = tid + 256*i;
                int row = q >> 5, c4 = q & 31;
                vb[i] = *(const uint4*)(Bp + (size_t)((kt >> 1) + 16 + row) * N + bn + c4*4);
            }
        }

        #pragma unroll
        for (int s = 0; s < 2; s++){
            int s8 = s * 8;
            unsigned bf[8][2];
            #pragma unroll
            for (int nt = 0; nt < 8; nt++){
                int col = wn*64 + nt*8 + g;
                bf[nt][0] = Bs2[s8+tg  ][col];
                bf[nt][1] = Bs2[s8+tg+4][col];
            }
            #pragma unroll
            for (int mt = 0; mt < 2; mt++){
                int mb = wm*32 + mt*16;
                unsigned a0 = As2[s8+tg  ][mb+g];
                unsigned a1 = As2[s8+tg  ][mb+8+g];
                unsigned a2 = As2[s8+tg+4][mb+g];
                unsigned a3 = As2[s8+tg+4][mb+8+g];
                #pragma unroll
                for (int nt = 0; nt < 8; nt++){
                    asm volatile(
                        "mma.sync.aligned.m16n8k16.row.col.f32.f16.f16.f32 "
                        "{%0,%1,%2,%3}, {%4,%5,%6,%7}, {%8,%9}, {%0,%1,%2,%3};"
                        : "+f"(c[mt][nt][0]), "+f"(c[mt][nt][1]),
                          "+f"(c[mt][nt][2]), "+f"(c[mt][nt][3])
                        : "r"(a0), "r"(a1), "r"(a2), "r"(a3),
                          "r"(bf[nt][0]), "r"(bf[nt][1]));
                }
            }
        }
        __syncthreads();
    }

    #pragma unroll
    for (int mt = 0; mt < 2; mt++){
        int row0 = bm + wm*32 + mt*16 + g;
        #pragma unroll
        for (int nt = 0; nt < 8; nt++){
            int col = bn + wn*64 + nt*8 + 2*tg;
            float b0 = 0.f, b1 = 0.f;
            if (bias){ b0 = bias[col]; b1 = bias[col+1]; }
            float2 v0, v1;
            v0.x = c[mt][nt][0]*inv_ascale + b0; v0.y = c[mt][nt][1]*inv_ascale + b1;
            v1.x = c[mt][nt][2]*inv_ascale + b0; v1.y = c[mt][nt][3]*inv_ascale + b1;
            if (act){ v0.x = lk(v0.x); v0.y = lk(v0.y); v1.x = lk(v1.x); v1.y = lk(v1.y); }
            if (OUTH){
                __half* C = (__half*)Cv + (size_t)blockIdx.z * sCz;
                *(__half2*)(C + (size_t)row0 * ldc + col)       = __floats2half2_rn(v0.x*oscale, v0.y*oscale);
                *(__half2*)(C + (size_t)(row0 + 8) * ldc + col) = __floats2half2_rn(v1.x*oscale, v1.y*oscale);
            } else {
                float* C = (float*)Cv + (size_t)blockIdx.z * sCz;
                *(float2*)(C + (size_t)row0 * ldc + col)       = v0;
                *(float2*)(C + (size_t)(row0 + 8) * ldc + col) = v1;
            }
        }
    }
}

// ---------------- fp16-input NT GEMM: C = (A[M,K] @ B[N,K]^T) * oscale ----------------
__global__ void __launch_bounds__(256) k_hmma_nt(
    const __half* __restrict__ A, const __half* __restrict__ B,
    float* __restrict__ C, int M, int N, int K, int ldc,
    long long sAz, long long sBz, long long sCz, float oscale)
{
    __shared__ unsigned As2[16][136];
    __shared__ unsigned Bs2[16][136];
    int z = blockIdx.z;
    A += (size_t)z * sAz; B += (size_t)z * sBz; C += (size_t)z * sCz;
    int bm = blockIdx.y * 128, bn = blockIdx.x * 128;
    int tid = threadIdx.x;
    int warp = tid >> 5, lane = tid & 31;
    int wm = warp & 3, wn = warp >> 2;
    int g = lane >> 2, tg = lane & 3;

    float c[2][8][4];
    #pragma unroll
    for (int mt = 0; mt < 2; mt++)
        #pragma unroll
        for (int nt = 0; nt < 8; nt++)
            #pragma unroll
            for (int i = 0; i < 4; i++) c[mt][nt][i] = 0.f;

    float4 va[2], vb[2];
    #pragma unroll
    for (int i = 0; i < 2; i++){
        int q = tid + 256*i;
        int r = q >> 2, cc = (q & 3) << 3;
        va[i] = *(const float4*)(A + (size_t)(bm + r) * K + cc);
        vb[i] = *(const float4*)(B + (size_t)(bn + r) * K + cc);
    }

    for (int kt = 0; kt < K; kt += 32){
        #pragma unroll
        for (int i = 0; i < 2; i++){
            int q = tid + 256*i;
            int r = q >> 2, cc = (q & 3) << 3;
            const unsigned* pa = (const unsigned*)&va[i];
            const unsigned* pb = (const unsigned*)&vb[i];
            int kh = cc >> 1;
            As2[kh  ][r] = pa[0]; As2[kh+1][r] = pa[1];
            As2[kh+2][r] = pa[2]; As2[kh+3][r] = pa[3];
            Bs2[kh  ][r] = pb[0]; Bs2[kh+1][r] = pb[1];
            Bs2[kh+2][r] = pb[2]; Bs2[kh+3][r] = pb[3];
        }
        __syncthreads();
        if (kt + 32 < K){
            #pragma unroll
            for (int i = 0; i < 2; i++){
                int q = tid + 256*i;
                int r = q >> 2, cc = (q & 3) << 3;
                va[i] = *(const float4*)(A + (size_t)(bm + r) * K + kt + 32 + cc);
                vb[i] = *(const float4*)(B + (size_t)(bn + r) * K + kt + 32 + cc);
            }
        }

        #pragma unroll
        for (int s = 0; s < 2; s++){
            int s8 = s * 8;
            unsigned bf[8][2];
            #pragma unroll
            for (int nt = 0; nt < 8; nt++){
                int col = wn*64 + nt*8 + g;
                bf[nt][0] = Bs2[s8+tg  ][col];
                bf[nt][1] = Bs2[s8+tg+4][col];
            }
            #pragma unroll
            for (int mt = 0; mt < 2; mt++){
                int mb = wm*32 + mt*16;
                unsigned a0 = As2[s8+tg  ][mb+g];
                unsigned a1 = As2[s8+tg  ][mb+8+g];
                unsigned a2 = As2[s8+tg+4][mb+g];
                unsigned a3 = As2[s8+tg+4][mb+8+g];
                #pragma unroll
                for (int nt = 0; nt < 8; nt++){
                    asm volatile(
                        "mma.sync.aligned.m16n8k16.row.col.f32.f16.f16.f32 "
                        "{%0,%1,%2,%3}, {%4,%5,%6,%7}, {%8,%9}, {%0,%1,%2,%3};"
                        : "+f"(c[mt][nt][0]), "+f"(c[mt][nt][1]),
                          "+f"(c[mt][nt][2]), "+f"(c[mt][nt][3])
                        : "r"(a0), "r"(a1), "r"(a2), "r"(a3),
                          "r"(bf[nt][0]), "r"(bf[nt][1]));
                }
            }
        }
        __syncthreads();
    }

    #pragma unroll
    for (int mt = 0; mt < 2; mt++){
        int row0 = bm + wm*32 + mt*16 + g;
        #pragma unroll
        for (int nt = 0; nt < 8; nt++){
            int col = bn + wn*64 + nt*8 + 2*tg;
            float2 v0, v1;
            v0.x = c[mt][nt][0]*oscale; v0.y = c[mt][nt][1]*oscale;
            v1.x = c[mt][nt][2]*oscale; v1.y = c[mt][nt][3]*oscale;
            __stcs((float2*)(C + (size_t)row0 * ldc + col), v0);
            __stcs((float2*)(C + (size_t)(row0 + 8) * ldc + col), v1);
        }
    }
}

// ---------------- w1/w2: Wh_l[b] @ att halves (both layers) ----------------
__global__ void k_watt(const float* __restrict__ Wh1, const float* __restrict__ at1,
                       const float* __restrict__ Wh2, const float* __restrict__ at2){
    int w = (blockIdx.x * blockDim.x + threadIdx.x) >> 5;
    int lane = threadIdx.x & 31;
    if (w >= 2*2*3*FF) return;
    int l    = w / (2*3*FF);
    int half = (w / (3*FF)) % 2;
    int b    = (w / FF) % 3, k = w % FF;
    const float* Wh  = l ? Wh2 : Wh1;
    const float* att = l ? at2 : at1;
    const float* row = Wh + (size_t)b*FF*FF + (size_t)k*FF;
    const float* av  = att + b*512 + half*256;
    float4 r0 = ((const float4*)row)[lane*2], r1 = ((const float4*)row)[lane*2+1];
    float4 a0 = ((const float4*)av )[lane*2], a1 = ((const float4*)av )[lane*2+1];
    float s = r0.x*a0.x + r0.y*a0.y + r0.z*a0.z + r0.w*a0.w
            + r1.x*a1.x + r1.y*a1.y + r1.z*a1.z + r1.w*a1.w;
    #pragma unroll
    for (int o = 16; o; o >>= 1) s += __shfl_xor_sync(0xffffffffu, s, o);
    if (lane == 0){
        if (half) g_w2[l][b][k] = s;
        else      g_w1[l][b][k] = s;
    }
}

// ---------------- s2[l][b][e] = hA[e] . w2[l][b] ----------------
__global__ void k_s2all(const float* __restrict__ hA){
    int w = (blockIdx.x * blockDim.x + threadIdx.x) >> 5;
    int lane = threadIdx.x & 31;
    if (w >= MM) return;
    int e = w;
    const float* row = hA + (size_t)e*FF;
    float4 r0 = ((const float4*)row)[lane*2], r1 = ((const float4*)row)[lane*2+1];
    #pragma unroll
    for (int q = 0; q < 6; q++){
        const float* w2 = g_w2[q/3][q%3];
        float4 a0 = ((const float4*)w2)[lane*2], a1 = ((const float4*)w2)[lane*2+1];
        float s = r0.x*a0.x + r0.y*a0.y + r0.z*a0.z + r0.w*a0.w
                + r1.x*a1.x + r1.y*a1.y + r1.z*a1.z + r1.w*a1.w;
        #pragma unroll
        for (int o = 16; o; o >>= 1) s += __shfl_xor_sync(0xffffffffu, s, o);
        if (lane == 0) g_s2[q/3][q%3][e] = s;
    }
}

// ---------------- s1[b][n] = h[n] . w1[l][b] ----------------
__global__ void k_s1(int l, const float* __restrict__ hsrc){
    int w = (blockIdx.x * blockDim.x + threadIdx.x) >> 5;
    int lane = threadIdx.x & 31;
    if (w >= NN) return;
    int n = w;
    const float4* hr = (const float4*)(hsrc + (size_t)n*FF);
    float4 v0 = hr[lane], v1 = hr[32+lane];
    #pragma unroll
    for (int b = 0; b < 3; b++){
        const float* w1 = g_w1[l][b];
        float4 a0 = ((const float4*)w1)[lane], a1 = ((const float4*)w1)[32+lane];
        float s = v0.x*a0.x + v0.y*a0.y + v0.z*a0.z + v0.w*a0.w
                + v1.x*a1.x + v1.y*a1.y + v1.z*a1.z + v1.w*a1.w;
        #pragma unroll
        for (int o = 16; o; o >>= 1) s += __shfl_xor_sync(0xffffffffu, s, o);
        if (lane == 0) g_s1[b][n] = s;
    }
}

// ---------------- stats: single-pass online softmax (+ D on layer 0) -> ninfo ----------------
__global__ void k_stats(int l, const float* __restrict__ hw, int computeD){
    int w = (blockIdx.x * blockDim.x + threadIdx.x) >> 5;
    int lane = threadIdx.x & 31;
    if (w >= 3*NN) return;
    int b = w / NN, n = w % NN;

    float s1n = g_s1[b][n];
    const float* s2b = g_s2[l][b];
    int beg = g_noff[b][n], end = g_noff[b][n+1];

    float mx = -1e30f, sum = 0.f, ds = 0.f;
    for (int p = beg + lane; p < end; p += 32){
        int e = __ldcs(&g_eiN[b][p]);
        float a = lk(s1n + s2b[e]);
        if (computeD) ds += hw[e];
        float mo = mx;
        mx = fmaxf(mx, a);
        sum = sum * __expf(mo - mx) + __expf(a - mx);
    }
    #pragma unroll
    for (int o = 16; o; o >>= 1){
        float mo2 = __shfl_xor_sync(0xffffffffu, mx, o);
        float so2 = __shfl_xor_sync(0xffffffffu, sum, o);
        float mn = fmaxf(mx, mo2);
        sum = sum * __expf(mx - mn) + so2 * __expf(mo2 - mn);
        mx = mn;
        if (computeD) ds += __shfl_xor_sync(0xffffffffu, ds, o);
    }
    if (lane == 0){
        float di;
        if (computeD){
            di = (ds > 0.f) ? 1.f/ds : 0.f;
            g_Dv[b][n] = di;
        } else {
            di = g_Dv[b][n];
        }
        if (end > beg) g_ninfo[b][n] = make_float4(s1n, mx, 1.f/sum, di);
        else           g_ninfo[b][n] = make_float4(s1n, 0.f, 0.f, 0.f);
    }
}

// ---------------- gather helpers ----------------
__device__ __forceinline__ void row_acc(const __half* base, int r, int lane, float c, float* acc){
    float4 raw = *(const float4*)(base + (size_t)r * FF + lane*8);
    const __half2* hp = (const __half2*)&raw;
    #pragma unroll
    for (int q = 0; q < 4; q++){
        float2 f = __half22float2(hp[q]);
        acc[2*q]   += c*f.x;
        acc[2*q+1] += c*f.y;
    }
}

// 8-way unrolled gather-accumulate over a warp-shuffled (row, coef) batch
__device__ __forceinline__ void gather_batch(const __half* base, int lane,
                                             int idxv, float coefv, int cnt, float* acc){
    int t = 0;
    for (; t + 8 <= cnt; t += 8){
        int r[8]; float cf[8];
        #pragma unroll
        for (int u = 0; u < 8; u++){
            r[u]  = __shfl_sync(0xffffffffu, idxv,  t+u);
            cf[u] = __shfl_sync(0xffffffffu, coefv, t+u);
        }
        float4 raw[8];
        #pragma unroll
        for (int u = 0; u < 8; u++)
            raw[u] = *(const float4*)(base + (size_t)r[u] * FF + lane*8);
        #pragma unroll
        for (int u = 0; u < 8; u++){
            const __half2* hp = (const __half2*)&raw[u];
            #pragma unroll
            for (int q = 0; q < 4; q++){
                float2 f = __half22float2(hp[q]);
                acc[2*q]   += cf[u]*f.x;
                acc[2*q+1] += cf[u]*f.y;
            }
        }
    }
    for (; t + 4 <= cnt; t += 4){
        int r[4]; float cf[4];
        #pragma unroll
        for (int u = 0; u < 4; u++){
            r[u]  = __shfl_sync(0xffffffffu, idxv,  t+u);
            cf[u] = __shfl_sync(0xffffffffu, coefv, t+u);
        }
        float4 raw[4];
        #pragma unroll
        for (int u = 0; u < 4; u++)
            raw[u] = *(const float4*)(base + (size_t)r[u] * FF + lane*8);
        #pragma unroll
        for (int u = 0; u < 4; u++){
            const __half2* hp = (const __half2*)&raw[u];
            #pragma unroll
            for (int q = 0; q < 4; q++){
                float2 f = __half22float2(hp[q]);
                acc[2*q]   += cf[u]*f.x;
                acc[2*q+1] += cf[u]*f.y;
            }
        }
    }
    for (; t < cnt; t++){
        int   r0 = __shfl_sync(0xffffffffu, idxv,  t);
        float c0 = __shfl_sync(0xffffffffu, coefv, t);
        row_acc(base, r0, lane, c0, acc);
    }
}

// ---------------- edge pass ----------------
__global__ void k_edge(int l){
    int w = (blockIdx.x * blockDim.x + threadIdx.x) >> 5;
    int lane = threadIdx.x & 31;
    if (w >= 3*MM) return;
    int b = w / MM, e = w % MM;
    int beg = g_eoff[b][e], end = g_eoff[b][e+1];
    float s2e = g_s2[l][b][e];
    const __half* xlb = g_xl[b];
    float acc[8] = {0,0,0,0,0,0,0,0};
    for (int base = beg; base < end; base += 32){
        int p = base + lane;
        int nrow = 0; float coef = 0.f;
        if (p < end){
            nrow = __ldcs(&g_niE[b][p]);
            float4 info = g_ninfo[b][nrow];
            coef = __expf(lk(info.x + s2e) - info.y) * info.z;
        }
        gather_batch(xlb, lane, nrow, coef, min(32, end - base), acc);
    }
    int ce = end - beg;
    float bi = (ce > 0) ? 1.f/(float)ce : 0.f;
    __half2 o[4];
    o[0] = __floats2half2_rn(bi*acc[0], bi*acc[1]);
    o[1] = __floats2half2_rn(bi*acc[2], bi*acc[3]);
    o[2] = __floats2half2_rn(bi*acc[4], bi*acc[5]);
    o[3] = __floats2half2_rn(bi*acc[6], bi*acc[7]);
    *(float4*)(g_m[b] + (size_t)e * FF + lane*8) = *(float4*)o;
}

// ---------------- node pass ----------------
__global__ void k_node(int l, const float* __restrict__ bc, float* __restrict__ hout, float invS){
    int w = (blockIdx.x * blockDim.x + threadIdx.x) >> 5;
    int lane = threadIdx.x & 31;
    if (w >= NN) return;
    int n = w;
    float t[8] = {0,0,0,0,0,0,0,0};
    #pragma unroll
    for (int b = 0; b < 3; b++){
        int beg = g_noff[b][n], end = g_noff[b][n+1];
        float4 info = g_ninfo[b][n];
        float s1n = info.x, mxn = info.y, rsn = info.z, di = info.w;
        const float* s2b = g_s2[l][b];
        const __half* mb = g_m[b];
        float a[8] = {0,0,0,0,0,0,0,0};
        for (int base = beg; base < end; base += 32){
            int p = base + lane;
            int er = 0; float coef = 0.f;
            if (p < end){
                er = __ldcs(&g_eiN[b][p]);
                coef = __expf(lk(s1n + s2b[er]) - mxn) * rsn;
            }
            gather_batch(mb, lane, er, coef, min(32, end - base), a);
        }
        #pragma unroll
        for (int i = 0; i < 8; i++) t[i] += di * a[i];
    }
    #pragma unroll
    for (int i = 0; i < 8; i++) t[i] *= invS;
    #pragma unroll
    for (int k = 0; k < 3; k++){
        float4 b0 = *(const float4*)(bc + k*256 + lane*8);
        float4 b1 = *(const float4*)(bc + k*256 + lane*8 + 4);
        t[0] += b0.x; t[1] += b0.y; t[2] += b0.z; t[3] += b0.w;
        t[4] += b1.x; t[5] += b1.y; t[6] += b1.z; t[7] += b1.w;
    }
    #pragma unroll
    for (int i = 0; i < 8; i++) t[i] = lk(t[i]);
    *(float4*)(hout + (size_t)n * FF + lane*8)     = make_float4(t[0], t[1], t[2], t[3]);
    *(float4*)(hout + (size_t)n * FF + lane*8 + 4) = make_float4(t[4], t[5], t[6], t[7]);
}

// ---------------- host launcher ----------------
static void* symaddr(const void* sym){ void* p = nullptr; cudaGetSymbolAddress(&p, sym); return p; }

extern "C" void kernel_launch(void* const* d_in, const int* in_sizes, int n_in,
                              void* d_out, int out_size){
    const float* g   = (const float*)d_in[0];
    const float* x   = (const float*)d_in[1];
    const float* hw  = (const float*)d_in[2];
    const float* hA  = (const float*)d_in[3];
    const int* ni0 = (const int*)d_in[4]; const int* ei0 = (const int*)d_in[5];
    const int* ni1 = (const int*)d_in[6]; const int* ei1 = (const int*)d_in[7];
    const int* ni2 = (const int*)d_in[8]; const int* ei2 = (const int*)d_in[9];
    const float* W0  = (const float*)d_in[10]; const float* b0  = (const float*)d_in[11];
    const float* Wh1 = (const float*)d_in[12]; const float* at1 = (const float*)d_in[13];
    const float* bc1 = (const float*)d_in[14];
    const float* W1  = (const float*)d_in[15]; const float* b1  = (const float*)d_in[16];
    const float* Wh2 = (const float*)d_in[17]; const float* at2 = (const float*)d_in[18];
    const float* bc2 = (const float*)d_in[19];
    const float* Wg  = (const float*)d_in[20]; const float* bg  = (const float*)d_in[21];
    const float* Wx  = (const float*)d_in[22]; const float* bx  = (const float*)d_in[23];
    float* out = (float*)d_out;

    float*    p_h     = (float*)symaddr(g_h);
    float*    p_h2    = (float*)symaddr(g_h2);
    void*     p_xl    = symaddr(g_xl);
    void*     p_newgh = symaddr(g_newgh);
    void*     p_xsh   = symaddr(g_xsh);
    const unsigned* pWp  = (const unsigned*)symaddr(g_Wp);
    const unsigned* pWpc = (const unsigned*)symaddr(g_Wpc);

    const float S1 = 1.f,    IS1 = 1.f;
    const float SK = 1024.f, ISK = 1.f/1024.f;

    cudaStream_t sB = 0;
    cudaEvent_t evF = 0, evJ = 0;
    cudaStreamCreateWithFlags(&sB, cudaStreamNonBlocking);
    cudaEventCreateWithFlags(&evF, cudaEventDisableTiming);
    cudaEventCreateWithFlags(&evJ, cudaEventDisableTiming);

    cudaEventRecord(evF, 0);
    cudaStreamWaitEvent(sB, evF, 0);

    // ---- side stream: CSR build ----
    k_zero<<<(3*(MM+1) + 255)/256, 256, 0, sB>>>();
    k_hist<<<(3*EE + 255)/256, 256, 0, sB>>>(ni0, ei0, ni1, ei1, ni2, ei2);
    k_scan<<<6, 1024, 0, sB>>>();
    k_scatter<<<(3*EE + 255)/256, 256, 0, sB>>>(ni0, ei0, ni1, ei1, ni2, ei2);
    cudaEventRecord(evJ, sB);

    // ---- main: weight prep + watt, layer0, hyper1-lin, s2, xs, s1(0) ----
    k_prepw<<<(4*3*32768 + 2*2*16384 + 255)/256, 256>>>(W0, Wh1, W1, Wh2, Wg, Wx);
    k_watt<<<(2*2*3*FF*32 + 255)/256, 256>>>(Wh1, at1, Wh2, at2);
    k_hmma<0><<<dim3(2,32,3), 256>>>(g, pWp + 0*98304, p_h, b0, 4096, 256, 256, 256,
                                     (long long)4096*256, 32768LL, (long long)4096*256, 256LL, 1, S1, IS1, 1.f);
    k_hmma<1><<<dim3(2,96,3), 256>>>(p_h, pWp + 1*98304, p_xl, nullptr, 12288, 256, 256, 256,
                                     0LL, 32768LL, (long long)12288*256, 0LL, 0, S1, IS1, 1.f);
    k_s2all<<<(MM*32 + 255)/256, 256>>>(hA);
    k_hmma<1><<<dim3(1,32,2), 256>>>(x, pWpc + 32768, p_xsh, bx + 128,
                                     4096, 128, 256, 128,
                                     0LL, 16384LL, (long long)4096*128, 128LL, 1, S1, IS1, 1.f);
    k_s1<<<(NN*32 + 255)/256, 256>>>(0, p_h);
    cudaStreamWaitEvent(0, evJ, 0);

    // ---- hyper1 ----
    k_stats<<<(3*NN*32 + 255)/256, 256>>>(0, hw, 1);
    k_edge<<<(3*MM*32 + 255)/256, 256>>>(0);
    k_node<<<(NN*32 + 255)/256, 256>>>(0, bc1, p_h, IS1);

    // ---- layer1 ----
    k_hmma<0><<<dim3(2,32,3), 256>>>(p_h, pWp + 2*98304, p_h2, b1, 4096, 256, 256, 256,
                                     (long long)4096*256, 32768LL, (long long)4096*256, 256LL, 1, SK, ISK, 1.f);
    k_s1<<<(NN*32 + 255)/256, 256>>>(1, p_h2);

    // ---- hyper2 ----
    k_hmma<1><<<dim3(2,96,3), 256>>>(p_h2, pWp + 3*98304, p_xl, nullptr, 12288, 256, 256, 256,
                                     0LL, 32768LL, (long long)12288*256, 0LL, 0, SK, ISK, 1024.f);
    k_stats<<<(3*NN*32 + 255)/256, 256>>>(1, hw, 0);
    k_edge<<<(3*MM*32 + 255)/256, 256>>>(1);
    k_node<<<(NN*32 + 255)/256, 256>>>(1, bc2, out + HOFF, ISK);

    // ---- new_g projection ----
    k_hmma<1><<<dim3(1,32,2), 256>>>(out + HOFF + (size_t)4096*256, pWpc + 0, p_newgh, bg + 128,
                                     4096, 128, 256, 128,
                                     (long long)4096*256, 16384LL, (long long)4096*128, 128LL, 1, SK, ISK, 1024.f);

    // ---- result ----
    k_hmma_nt<<<dim3(32,32,2), 256>>>((const __half*)p_xsh, (const __half*)p_newgh, out,
                                      4096, 4096, 128, 8192,
                                      (long long)4096*128, (long long)4096*128, 4096LL, ISK);
}

// round 15
// speedup vs baseline: 1.0284x; 1.0284x over previous
#include <cuda_runtime.h>
#include <cuda_fp16.h>
#include <math.h>

#define NN 12288
#define SS 4096
#define MM 16384
#define EE 393216
#define FF 256
#define CC 128
#define SLOPE 0.2f
#define HOFF 33554432   // 4096*8192, h output starts here

// ---------------- scratch (static device memory; no allocation) ----------------
__device__ float    g_h  [NN*FF];
__device__ float    g_h2 [NN*FF];
__device__ __half   g_xl [3][NN*FF];    // fp16 rows for gather (layer1: scaled x1024)
__device__ __half   g_m  [3][MM*FF];    // fp16 rows for gather (layer1: scaled x1024)
__device__ float    g_w1 [2][3][FF];
__device__ float    g_w2 [2][3][FF];
__device__ float    g_s1 [3][NN];
__device__ float    g_s2 [2][3][MM];
__device__ float4   g_ninfo[3][NN];     // (s1, max, 1/sum, 1/D)
__device__ float    g_Dv [3][NN];
__device__ int      g_noff[3][NN+1];
__device__ int      g_eoff[3][MM+1];
__device__ int      g_ncur[3][NN];
__device__ int      g_ecur[3][MM];
__device__ int      g_eiN [3][EE];
__device__ int      g_niE [3][EE];
__device__ __half   g_newgh[2][SS*CC];
__device__ __half   g_xsh  [2][SS*CC];
__device__ unsigned g_Wp [4][3][32768];
__device__ unsigned g_Wpc[2][2][16384];

__device__ __forceinline__ float lk(float v){ return v >= 0.f ? v : SLOPE * v; }
__device__ __forceinline__ unsigned packh2(float x, float y){
    __half2 h = __floats2half2_rn(x, y);
    return *(unsigned*)&h;
}

// ---------------- weight prep: fp32 -> packed half2 [K/2][N] ----------------
__global__ void k_prepw(const float* __restrict__ W0, const float* __restrict__ Wh1,
                        const float* __restrict__ W1, const float* __restrict__ Wh2,
                        const float* __restrict__ Wg, const float* __restrict__ Wx){
    int i = blockIdx.x * blockDim.x + threadIdx.x;
    if (i < 4*3*32768){
        int set = i / 98304;
        int r   = i % 98304;
        int z   = r / 32768;
        int off = r % 32768;
        int k2  = off >> 8, n = off & 255;
        const float* W = (set==0)?W0:(set==1)?Wh1:(set==2)?W1:Wh2;
        const float* s = W + (size_t)z*65536 + (size_t)(2*k2)*256 + n;
        g_Wp[set][z][off] = packh2(s[0], s[256]);
    } else {
        int j = i - 4*3*32768;
        if (j < 2*2*16384){
            int set = j / 32768;
            int r   = j % 32768;
            int z   = r / 16384;
            int off = r % 16384;
            int k2  = off >> 7, n = off & 127;
            const float* W = set ? Wx : Wg;
            const float* s = W + (size_t)(z+1)*32768 + (size_t)(2*k2)*128 + n;
            g_Wpc[set][z][off] = packh2(s[0], s[128]);
        }
    }
}

// ---------------- setup: counting-sort CSR build ----------------
__global__ void k_zero(){
    int i = blockIdx.x * blockDim.x + threadIdx.x;
    if (i < 3*(NN+1)) ((int*)g_noff)[i] = 0;
    if (i < 3*(MM+1)) ((int*)g_eoff)[i] = 0;
}

__global__ void k_hist(const int* __restrict__ ni0, const int* __restrict__ ei0,
                       const int* __restrict__ ni1, const int* __restrict__ ei1,
                       const int* __restrict__ ni2, const int* __restrict__ ei2){
    int idx = blockIdx.x * blockDim.x + threadIdx.x;
    if (idx >= 3*EE) return;
    int b = idx / EE, j = idx % EE;
    const int* ni = (b==0) ? ni0 : (b==1) ? ni1 : ni2;
    const int* ei = (b==0) ? ei0 : (b==1) ? ei1 : ei2;
    atomicAdd(&g_noff[b][ni[j]+1], 1);
    atomicAdd(&g_eoff[b][ei[j]+1], 1);
}

__global__ void k_scan(){
    int bid = blockIdx.x;
    int *arr, *cur; int len;
    if (bid < 3){ arr = g_noff[bid];   cur = g_ncur[bid];   len = NN+1; }
    else        { arr = g_eoff[bid-3]; cur = g_ecur[bid-3]; len = MM+1; }
    __shared__ int wsum[32];
    int lane = threadIdx.x & 31, wid = threadIdx.x >> 5;
    int carry = 0;
    for (int base = 0; base < len; base += 1024){
        int i = base + threadIdx.x;
        int v = (i < len) ? arr[i] : 0;
        int s = v;
        #pragma unroll
        for (int o = 1; o < 32; o <<= 1){
            int t = __shfl_up_sync(0xffffffffu, s, o);
            if (lane >= o) s += t;
        }
        if (lane == 31) wsum[wid] = s;
        __syncthreads();
        if (wid == 0){
            int ws = wsum[lane];
            #pragma unroll
            for (int o = 1; o < 32; o <<= 1){
                int t = __shfl_up_sync(0xffffffffu, ws, o);
                if (lane >= o) ws += t;
            }
            wsum[lane] = ws;
        }
        __syncthreads();
        int incl = s + (wid ? wsum[wid-1] : 0) + carry;
        int tot = wsum[31];
        if (i < len){ arr[i] = incl; if (i < len-1) cur[i] = incl; }
        __syncthreads();
        carry += tot;
    }
}

__global__ void k_scatter(const int* __restrict__ ni0, const int* __restrict__ ei0,
                          const int* __restrict__ ni1, const int* __restrict__ ei1,
                          const int* __restrict__ ni2, const int* __restrict__ ei2){
    int idx = blockIdx.x * blockDim.x + threadIdx.x;
    if (idx >= 3*EE) return;
    int b = idx / EE, j = idx % EE;
    const int* ni = (b==0) ? ni0 : (b==1) ? ni1 : ni2;
    const int* ei = (b==0) ? ei0 : (b==1) ? ei1 : ei2;
    int n = ni[j], e = ei[j];
    int pn = atomicAdd(&g_ncur[b][n], 1); g_eiN[b][pn] = e;
    int pe = atomicAdd(&g_ecur[b][e], 1); g_niE[b][pe] = n;
}

// ---------------- fp16 tensor-core GEMM (NN), packed-fp16 B, reg double-buffered ----------------
template<int OUTH>
__global__ void __launch_bounds__(256) k_hmma(
    const float* __restrict__ A, const unsigned* __restrict__ Bp,
    void* __restrict__ Cv, const float* __restrict__ bias,
    int M, int N, int K, int ldc,
    long long sAz, long long sBz, long long sCz, long long sbz,
    int act, float ascale, float inv_ascale, float oscale)
{
    __shared__ unsigned As2[16][136];
    __shared__ unsigned Bs2[16][136];
    int z = blockIdx.z;
    A += (size_t)z * sAz; Bp += (size_t)z * sBz;
    if (bias) bias += (size_t)z * sbz;
    int bm = blockIdx.y * 128, bn = blockIdx.x * 128;
    int tid = threadIdx.x;
    int warp = tid >> 5, lane = tid & 31;
    int wm = warp & 3, wn = warp >> 2;
    int g = lane >> 2, tg = lane & 3;

    float c[2][8][4];
    #pragma unroll
    for (int mt = 0; mt < 2; mt++)
        #pragma unroll
        for (int nt = 0; nt < 8; nt++)
            #pragma unroll
            for (int i = 0; i < 4; i++) c[mt][nt][i] = 0.f;

    float4 va[4]; uint4 vb[2];
    #pragma unroll
    for (int i = 0; i < 4; i++){
        int q = tid + 256*i;
        int r = q >> 3, cc = (q & 7) << 2;
        va[i] = *(const float4*)(A + (size_t)(bm + r) * K + cc);
    }
    #pragma unroll
    for (int i = 0; i < 2; i++){
        int q = tid + 256*i;
        int row = q >> 5, c4 = q & 31;
        vb[i] = *(const uint4*)(Bp + (size_t)row * N + bn + c4*4);
    }

    for (int kt = 0; kt < K; kt += 32){
        #pragma unroll
        for (int i = 0; i < 4; i++){
            int q = tid + 256*i;
            int r = q >> 3, cc = (q & 7) << 2;
            As2[(cc>>1)  ][r] = packh2(va[i].x*ascale, va[i].y*ascale);
            As2[(cc>>1)+1][r] = packh2(va[i].z*ascale, va[i].w*ascale);
        }
        #pragma unroll
        for (int i = 0; i < 2; i++){
            int q = tid + 256*i;
            int row = q >> 5, c4 = q & 31;
            *(uint4*)&Bs2[row][c4*4] = vb[i];
        }
        __syncthreads();
        if (kt + 32 < K){
            #pragma unroll
            for (int i = 0; i < 4; i++){
                int q = tid + 256*i;
                int r = q >> 3, cc = (q & 7) << 2;
                va[i] = *(const float4*)(A + (size_t)(bm + r) * K + kt + 32 + cc);
            }
            #pragma unroll
            for (int i = 0; i < 2; i++){
                int q = tid + 256*i;
                int row = q >> 5, c4 = q & 31;
                vb[i] = *(const uint4*)(Bp + (size_t)((kt >> 1) + 16 + row) * N + bn + c4*4);
            }
        }

        #pragma unroll
        for (int s = 0; s < 2; s++){
            int s8 = s * 8;
            unsigned bf[8][2];
            #pragma unroll
            for (int nt = 0; nt < 8; nt++){
                int col = wn*64 + nt*8 + g;
                bf[nt][0] = Bs2[s8+tg  ][col];
                bf[nt][1] = Bs2[s8+tg+4][col];
            }
            #pragma unroll
            for (int mt = 0; mt < 2; mt++){
                int mb = wm*32 + mt*16;
                unsigned a0 = As2[s8+tg  ][mb+g];
                unsigned a1 = As2[s8+tg  ][mb+8+g];
                unsigned a2 = As2[s8+tg+4][mb+g];
                unsigned a3 = As2[s8+tg+4][mb+8+g];
                #pragma unroll
                for (int nt = 0; nt < 8; nt++){
                    asm volatile(
                        "mma.sync.aligned.m16n8k16.row.col.f32.f16.f16.f32 "
                        "{%0,%1,%2,%3}, {%4,%5,%6,%7}, {%8,%9}, {%0,%1,%2,%3};"
                        : "+f"(c[mt][nt][0]), "+f"(c[mt][nt][1]),
                          "+f"(c[mt][nt][2]), "+f"(c[mt][nt][3])
                        : "r"(a0), "r"(a1), "r"(a2), "r"(a3),
                          "r"(bf[nt][0]), "r"(bf[nt][1]));
                }
            }
        }
        __syncthreads();
    }

    #pragma unroll
    for (int mt = 0; mt < 2; mt++){
        int row0 = bm + wm*32 + mt*16 + g;
        #pragma unroll
        for (int nt = 0; nt < 8; nt++){
            int col = bn + wn*64 + nt*8 + 2*tg;
            float b0 = 0.f, b1 = 0.f;
            if (bias){ b0 = bias[col]; b1 = bias[col+1]; }
            float2 v0, v1;
            v0.x = c[mt][nt][0]*inv_ascale + b0; v0.y = c[mt][nt][1]*inv_ascale + b1;
            v1.x = c[mt][nt][2]*inv_ascale + b0; v1.y = c[mt][nt][3]*inv_ascale + b1;
            if (act){ v0.x = lk(v0.x); v0.y = lk(v0.y); v1.x = lk(v1.x); v1.y = lk(v1.y); }
            if (OUTH){
                __half* C = (__half*)Cv + (size_t)blockIdx.z * sCz;
                *(__half2*)(C + (size_t)row0 * ldc + col)       = __floats2half2_rn(v0.x*oscale, v0.y*oscale);
                *(__half2*)(C + (size_t)(row0 + 8) * ldc + col) = __floats2half2_rn(v1.x*oscale, v1.y*oscale);
            } else {
                float* C = (float*)Cv + (size_t)blockIdx.z * sCz;
                *(float2*)(C + (size_t)row0 * ldc + col)       = v0;
                *(float2*)(C + (size_t)(row0 + 8) * ldc + col) = v1;
            }
        }
    }
}

// ---------------- fp16-input NT GEMM: C = (A[M,K] @ B[N,K]^T) * oscale ----------------
__global__ void __launch_bounds__(256) k_hmma_nt(
    const __half* __restrict__ A, const __half* __restrict__ B,
    float* __restrict__ C, int M, int N, int K, int ldc,
    long long sAz, long long sBz, long long sCz, float oscale)
{
    __shared__ unsigned As2[16][136];
    __shared__ unsigned Bs2[16][136];
    int z = blockIdx.z;
    A += (size_t)z * sAz; B += (size_t)z * sBz; C += (size_t)z * sCz;
    int bm = blockIdx.y * 128, bn = blockIdx.x * 128;
    int tid = threadIdx.x;
    int warp = tid >> 5, lane = tid & 31;
    int wm = warp & 3, wn = warp >> 2;
    int g = lane >> 2, tg = lane & 3;

    float c[2][8][4];
    #pragma unroll
    for (int mt = 0; mt < 2; mt++)
        #pragma unroll
        for (int nt = 0; nt < 8; nt++)
            #pragma unroll
            for (int i = 0; i < 4; i++) c[mt][nt][i] = 0.f;

    float4 va[2], vb[2];
    #pragma unroll
    for (int i = 0; i < 2; i++){
        int q = tid + 256*i;
        int r = q >> 2, cc = (q & 3) << 3;
        va[i] = *(const float4*)(A + (size_t)(bm + r) * K + cc);
        vb[i] = *(const float4*)(B + (size_t)(bn + r) * K + cc);
    }

    for (int kt = 0; kt < K; kt += 32){
        #pragma unroll
        for (int i = 0; i < 2; i++){
            int q = tid + 256*i;
            int r = q >> 2, cc = (q & 3) << 3;
            const unsigned* pa = (const unsigned*)&va[i];
            const unsigned* pb = (const unsigned*)&vb[i];
            int kh = cc >> 1;
            As2[kh  ][r] = pa[0]; As2[kh+1][r] = pa[1];
            As2[kh+2][r] = pa[2]; As2[kh+3][r] = pa[3];
            Bs2[kh  ][r] = pb[0]; Bs2[kh+1][r] = pb[1];
            Bs2[kh+2][r] = pb[2]; Bs2[kh+3][r] = pb[3];
        }
        __syncthreads();
        if (kt + 32 < K){
            #pragma unroll
            for (int i = 0; i < 2; i++){
                int q = tid + 256*i;
                int r = q >> 2, cc = (q & 3) << 3;
                va[i] = *(const float4*)(A + (size_t)(bm + r) * K + kt + 32 + cc);
                vb[i] = *(const float4*)(B + (size_t)(bn + r) * K + kt + 32 + cc);
            }
        }

        #pragma unroll
        for (int s = 0; s < 2; s++){
            int s8 = s * 8;
            unsigned bf[8][2];
            #pragma unroll
            for (int nt = 0; nt < 8; nt++){
                int col = wn*64 + nt*8 + g;
                bf[nt][0] = Bs2[s8+tg  ][col];
                bf[nt][1] = Bs2[s8+tg+4][col];
            }
            #pragma unroll
            for (int mt = 0; mt < 2; mt++){
                int mb = wm*32 + mt*16;
                unsigned a0 = As2[s8+tg  ][mb+g];
                unsigned a1 = As2[s8+tg  ][mb+8+g];
                unsigned a2 = As2[s8+tg+4][mb+g];
                unsigned a3 = As2[s8+tg+4][mb+8+g];
                #pragma unroll
                for (int nt = 0; nt < 8; nt++){
                    asm volatile(
                        "mma.sync.aligned.m16n8k16.row.col.f32.f16.f16.f32 "
                        "{%0,%1,%2,%3}, {%4,%5,%6,%7}, {%8,%9}, {%0,%1,%2,%3};"
                        : "+f"(c[mt][nt][0]), "+f"(c[mt][nt][1]),
                          "+f"(c[mt][nt][2]), "+f"(c[mt][nt][3])
                        : "r"(a0), "r"(a1), "r"(a2), "r"(a3),
                          "r"(bf[nt][0]), "r"(bf[nt][1]));
                }
            }
        }
        __syncthreads();
    }

    #pragma unroll
    for (int mt = 0; mt < 2; mt++){
        int row0 = bm + wm*32 + mt*16 + g;
        #pragma unroll
        for (int nt = 0; nt < 8; nt++){
            int col = bn + wn*64 + nt*8 + 2*tg;
            float2 v0, v1;
            v0.x = c[mt][nt][0]*oscale; v0.y = c[mt][nt][1]*oscale;
            v1.x = c[mt][nt][2]*oscale; v1.y = c[mt][nt][3]*oscale;
            __stcs((float2*)(C + (size_t)row0 * ldc + col), v0);
            __stcs((float2*)(C + (size_t)(row0 + 8) * ldc + col), v1);
        }
    }
}

// ---------------- w1/w2: Wh_l[b] @ att halves (both layers) ----------------
__global__ void k_watt(const float* __restrict__ Wh1, const float* __restrict__ at1,
                       const float* __restrict__ Wh2, const float* __restrict__ at2){
    int w = (blockIdx.x * blockDim.x + threadIdx.x) >> 5;
    int lane = threadIdx.x & 31;
    if (w >= 2*2*3*FF) return;
    int l    = w / (2*3*FF);
    int half = (w / (3*FF)) % 2;
    int b    = (w / FF) % 3, k = w % FF;
    const float* Wh  = l ? Wh2 : Wh1;
    const float* att = l ? at2 : at1;
    const float* row = Wh + (size_t)b*FF*FF + (size_t)k*FF;
    const float* av  = att + b*512 + half*256;
    float4 r0 = ((const float4*)row)[lane*2], r1 = ((const float4*)row)[lane*2+1];
    float4 a0 = ((const float4*)av )[lane*2], a1 = ((const float4*)av )[lane*2+1];
    float s = r0.x*a0.x + r0.y*a0.y + r0.z*a0.z + r0.w*a0.w
            + r1.x*a1.x + r1.y*a1.y + r1.z*a1.z + r1.w*a1.w;
    #pragma unroll
    for (int o = 16; o; o >>= 1) s += __shfl_xor_sync(0xffffffffu, s, o);
    if (lane == 0){
        if (half) g_w2[l][b][k] = s;
        else      g_w1[l][b][k] = s;
    }
}

// ---------------- s2[l][b][e] = hA[e] . w2[l][b] ----------------
__global__ void k_s2all(const float* __restrict__ hA){
    int w = (blockIdx.x * blockDim.x + threadIdx.x) >> 5;
    int lane = threadIdx.x & 31;
    if (w >= MM) return;
    int e = w;
    const float* row = hA + (size_t)e*FF;
    float4 r0 = ((const float4*)row)[lane*2], r1 = ((const float4*)row)[lane*2+1];
    #pragma unroll
    for (int q = 0; q < 6; q++){
        const float* w2 = g_w2[q/3][q%3];
        float4 a0 = ((const float4*)w2)[lane*2], a1 = ((const float4*)w2)[lane*2+1];
        float s = r0.x*a0.x + r0.y*a0.y + r0.z*a0.z + r0.w*a0.w
                + r1.x*a1.x + r1.y*a1.y + r1.z*a1.z + r1.w*a1.w;
        #pragma unroll
        for (int o = 16; o; o >>= 1) s += __shfl_xor_sync(0xffffffffu, s, o);
        if (lane == 0) g_s2[q/3][q%3][e] = s;
    }
}

// ---------------- s1[b][n] = h[n] . w1[l][b] ----------------
__global__ void k_s1(int l, const float* __restrict__ hsrc){
    int w = (blockIdx.x * blockDim.x + threadIdx.x) >> 5;
    int lane = threadIdx.x & 31;
    if (w >= NN) return;
    int n = w;
    const float4* hr = (const float4*)(hsrc + (size_t)n*FF);
    float4 v0 = hr[lane], v1 = hr[32+lane];
    #pragma unroll
    for (int b = 0; b < 3; b++){
        const float* w1 = g_w1[l][b];
        float4 a0 = ((const float4*)w1)[lane], a1 = ((const float4*)w1)[32+lane];
        float s = v0.x*a0.x + v0.y*a0.y + v0.z*a0.z + v0.w*a0.w
                + v1.x*a1.x + v1.y*a1.y + v1.z*a1.z + v1.w*a1.w;
        #pragma unroll
        for (int o = 16; o; o >>= 1) s += __shfl_xor_sync(0xffffffffu, s, o);
        if (lane == 0) g_s1[b][n] = s;
    }
}

// ---------------- stats: single-pass online softmax (+ D on layer 0) -> ninfo ----------------
__global__ void k_stats(int l, const float* __restrict__ hw, int computeD){
    int w = (blockIdx.x * blockDim.x + threadIdx.x) >> 5;
    int lane = threadIdx.x & 31;
    if (w >= 3*NN) return;
    int b = w / NN, n = w % NN;

    float s1n = g_s1[b][n];
    const float* s2b = g_s2[l][b];
    int beg = g_noff[b][n], end = g_noff[b][n+1];

    float mx = -1e30f, sum = 0.f, ds = 0.f;
    for (int p = beg + lane; p < end; p += 32){
        int e = __ldcs(&g_eiN[b][p]);
        float a = lk(s1n + s2b[e]);
        if (computeD) ds += hw[e];
        float mo = mx;
        mx = fmaxf(mx, a);
        sum = sum * __expf(mo - mx) + __expf(a - mx);
    }
    #pragma unroll
    for (int o = 16; o; o >>= 1){
        float mo2 = __shfl_xor_sync(0xffffffffu, mx, o);
        float so2 = __shfl_xor_sync(0xffffffffu, sum, o);
        float mn = fmaxf(mx, mo2);
        sum = sum * __expf(mx - mn) + so2 * __expf(mo2 - mn);
        mx = mn;
        if (computeD) ds += __shfl_xor_sync(0xffffffffu, ds, o);
    }
    if (lane == 0){
        float di;
        if (computeD){
            di = (ds > 0.f) ? 1.f/ds : 0.f;
            g_Dv[b][n] = di;
        } else {
            di = g_Dv[b][n];
        }
        if (end > beg) g_ninfo[b][n] = make_float4(s1n, mx, 1.f/sum, di);
        else           g_ninfo[b][n] = make_float4(s1n, 0.f, 0.f, 0.f);
    }
}

// ---------------- gather helper: accumulate one row into acc[8] ----------------
__device__ __forceinline__ void row_acc(const __half* base, int r, int lane, float c, float* acc){
    float4 raw = *(const float4*)(base + (size_t)r * FF + lane*8);
    const __half2* hp = (const __half2*)&raw;
    #pragma unroll
    for (int q = 0; q < 4; q++){
        float2 f = __half22float2(hp[q]);
        acc[2*q]   += c*f.x;
        acc[2*q+1] += c*f.y;
    }
}

// ---------------- edge pass: 4-way unrolled gather ----------------
__global__ void k_edge(int l){
    int w = (blockIdx.x * blockDim.x + threadIdx.x) >> 5;
    int lane = threadIdx.x & 31;
    if (w >= 3*MM) return;
    int b = w / MM, e = w % MM;
    int beg = g_eoff[b][e], end = g_eoff[b][e+1];
    float s2e = g_s2[l][b][e];
    const __half* xlb = g_xl[b];
    float acc[8] = {0,0,0,0,0,0,0,0};
    for (int base = beg; base < end; base += 32){
        int p = base + lane;
        int nrow = 0; float coef = 0.f;
        if (p < end){
            nrow = __ldcs(&g_niE[b][p]);
            float4 info = g_ninfo[b][nrow];
            coef = __expf(lk(info.x + s2e) - info.y) * info.z;
        }
        int cnt = min(32, end - base);
        int t = 0;
        for (; t + 4 <= cnt; t += 4){
            int   r0 = __shfl_sync(0xffffffffu, nrow, t);
            float c0 = __shfl_sync(0xffffffffu, coef, t);
            int   r1 = __shfl_sync(0xffffffffu, nrow, t+1);
            float c1 = __shfl_sync(0xffffffffu, coef, t+1);
            int   r2 = __shfl_sync(0xffffffffu, nrow, t+2);
            float c2 = __shfl_sync(0xffffffffu, coef, t+2);
            int   r3 = __shfl_sync(0xffffffffu, nrow, t+3);
            float c3 = __shfl_sync(0xffffffffu, coef, t+3);
            float4 raw0 = *(const float4*)(xlb + (size_t)r0 * FF + lane*8);
            float4 raw1 = *(const float4*)(xlb + (size_t)r1 * FF + lane*8);
            float4 raw2 = *(const float4*)(xlb + (size_t)r2 * FF + lane*8);
            float4 raw3 = *(const float4*)(xlb + (size_t)r3 * FF + lane*8);
            const __half2* h0 = (const __half2*)&raw0;
            const __half2* h1 = (const __half2*)&raw1;
            const __half2* h2 = (const __half2*)&raw2;
            const __half2* h3 = (const __half2*)&raw3;
            #pragma unroll
            for (int q = 0; q < 4; q++){
                float2 f0 = __half22float2(h0[q]);
                float2 f1 = __half22float2(h1[q]);
                float2 f2 = __half22float2(h2[q]);
                float2 f3 = __half22float2(h3[q]);
                acc[2*q]   += c0*f0.x + c1*f1.x + c2*f2.x + c3*f3.x;
                acc[2*q+1] += c0*f0.y + c1*f1.y + c2*f2.y + c3*f3.y;
            }
        }
        for (; t < cnt; t++){
            int   r0 = __shfl_sync(0xffffffffu, nrow, t);
            float c0 = __shfl_sync(0xffffffffu, coef, t);
            row_acc(xlb, r0, lane, c0, acc);
        }
    }
    int ce = end - beg;
    float bi = (ce > 0) ? 1.f/(float)ce : 0.f;
    __half2 o[4];
    o[0] = __floats2half2_rn(bi*acc[0], bi*acc[1]);
    o[1] = __floats2half2_rn(bi*acc[2], bi*acc[3]);
    o[2] = __floats2half2_rn(bi*acc[4], bi*acc[5]);
    o[3] = __floats2half2_rn(bi*acc[6], bi*acc[7]);
    *(float4*)(g_m[b] + (size_t)e * FF + lane*8) = *(float4*)o;
}

// ---------------- node pass: 4-way unrolled ----------------
__global__ void k_node(int l, const float* __restrict__ bc, float* __restrict__ hout, float invS){
    int w = (blockIdx.x * blockDim.x + threadIdx.x) >> 5;
    int lane = threadIdx.x & 31;
    if (w >= NN) return;
    int n = w;
    float t[8] = {0,0,0,0,0,0,0,0};
    #pragma unroll
    for (int b = 0; b < 3; b++){
        int beg = g_noff[b][n], end = g_noff[b][n+1];
        float4 info = g_ninfo[b][n];
        float s1n = info.x, mxn = info.y, rsn = info.z, di = info.w;
        const float* s2b = g_s2[l][b];
        const __half* mb = g_m[b];
        float a[8] = {0,0,0,0,0,0,0,0};
        for (int base = beg; base < end; base += 32){
            int p = base + lane;
            int er = 0; float coef = 0.f;
            if (p < end){
                er = __ldcs(&g_eiN[b][p]);
                coef = __expf(lk(s1n + s2b[er]) - mxn) * rsn;
            }
            int cnt = min(32, end - base);
            int t2 = 0;
            for (; t2 + 4 <= cnt; t2 += 4){
                int   r0 = __shfl_sync(0xffffffffu, er, t2);
                float c0 = __shfl_sync(0xffffffffu, coef, t2);
                int   r1 = __shfl_sync(0xffffffffu, er, t2+1);
                float c1 = __shfl_sync(0xffffffffu, coef, t2+1);
                int   r2 = __shfl_sync(0xffffffffu, er, t2+2);
                float c2 = __shfl_sync(0xffffffffu, coef, t2+2);
                int   r3 = __shfl_sync(0xffffffffu, er, t2+3);
                float c3 = __shfl_sync(0xffffffffu, coef, t2+3);
                float4 raw0 = *(const float4*)(mb + (size_t)r0 * FF + lane*8);
                float4 raw1 = *(const float4*)(mb + (size_t)r1 * FF + lane*8);
                float4 raw2 = *(const float4*)(mb + (size_t)r2 * FF + lane*8);
                float4 raw3 = *(const float4*)(mb + (size_t)r3 * FF + lane*8);
                const __half2* h0 = (const __half2*)&raw0;
                const __half2* h1 = (const __half2*)&raw1;
                const __half2* h2 = (const __half2*)&raw2;
                const __half2* h3 = (const __half2*)&raw3;
                #pragma unroll
                for (int q = 0; q < 4; q++){
                    float2 f0 = __half22float2(h0[q]);
                    float2 f1 = __half22float2(h1[q]);
                    float2 f2 = __half22float2(h2[q]);
                    float2 f3 = __half22float2(h3[q]);
                    a[2*q]   += c0*f0.x + c1*f1.x + c2*f2.x + c3*f3.x;
                    a[2*q+1] += c0*f0.y + c1*f1.y + c2*f2.y + c3*f3.y;
                }
            }
            for (; t2 < cnt; t2++){
                int   r0 = __shfl_sync(0xffffffffu, er, t2);
                float c0 = __shfl_sync(0xffffffffu, coef, t2);
                row_acc(mb, r0, lane, c0, a);
            }
        }
        #pragma unroll
        for (int i = 0; i < 8; i++) t[i] += di * a[i];
    }
    #pragma unroll
    for (int i = 0; i < 8; i++) t[i] *= invS;
    #pragma unroll
    for (int k = 0; k < 3; k++){
        float4 b0 = *(const float4*)(bc + k*256 + lane*8);
        float4 b1 = *(const float4*)(bc + k*256 + lane*8 + 4);
        t[0] += b0.x; t[1] += b0.y; t[2] += b0.z; t[3] += b0.w;
        t[4] += b1.x; t[5] += b1.y; t[6] += b1.z; t[7] += b1.w;
    }
    #pragma unroll
    for (int i = 0; i < 8; i++) t[i] = lk(t[i]);
    *(float4*)(hout + (size_t)n * FF + lane*8)     = make_float4(t[0], t[1], t[2], t[3]);
    *(float4*)(hout + (size_t)n * FF + lane*8 + 4) = make_float4(t[4], t[5], t[6], t[7]);
}

// ---------------- host launcher ----------------
static void* symaddr(const void* sym){ void* p = nullptr; cudaGetSymbolAddress(&p, sym); return p; }

extern "C" void kernel_launch(void* const* d_in, const int* in_sizes, int n_in,
                              void* d_out, int out_size){
    const float* g   = (const float*)d_in[0];
    const float* x   = (const float*)d_in[1];
    const float* hw  = (const float*)d_in[2];
    const float* hA  = (const float*)d_in[3];
    const int* ni0 = (const int*)d_in[4]; const int* ei0 = (const int*)d_in[5];
    const int* ni1 = (const int*)d_in[6]; const int* ei1 = (const int*)d_in[7];
    const int* ni2 = (const int*)d_in[8]; const int* ei2 = (const int*)d_in[9];
    const float* W0  = (const float*)d_in[10]; const float* b0  = (const float*)d_in[11];
    const float* Wh1 = (const float*)d_in[12]; const float* at1 = (const float*)d_in[13];
    const float* bc1 = (const float*)d_in[14];
    const float* W1  = (const float*)d_in[15]; const float* b1  = (const float*)d_in[16];
    const float* Wh2 = (const float*)d_in[17]; const float* at2 = (const float*)d_in[18];
    const float* bc2 = (const float*)d_in[19];
    const float* Wg  = (const float*)d_in[20]; const float* bg  = (const float*)d_in[21];
    const float* Wx  = (const float*)d_in[22]; const float* bx  = (const float*)d_in[23];
    float* out = (float*)d_out;

    float*    p_h     = (float*)symaddr(g_h);
    float*    p_h2    = (float*)symaddr(g_h2);
    void*     p_xl    = symaddr(g_xl);
    void*     p_newgh = symaddr(g_newgh);
    void*     p_xsh   = symaddr(g_xsh);
    const unsigned* pWp  = (const unsigned*)symaddr(g_Wp);
    const unsigned* pWpc = (const unsigned*)symaddr(g_Wpc);

    const float S1 = 1.f,    IS1 = 1.f;
    const float SK = 1024.f, ISK = 1.f/1024.f;

    cudaStream_t sB = 0;
    cudaEvent_t evF = 0, evJ = 0;
    cudaStreamCreateWithFlags(&sB, cudaStreamNonBlocking);
    cudaEventCreateWithFlags(&evF, cudaEventDisableTiming);
    cudaEventCreateWithFlags(&evJ, cudaEventDisableTiming);

    cudaEventRecord(evF, 0);
    cudaStreamWaitEvent(sB, evF, 0);

    // ---- side stream: CSR build ----
    k_zero<<<(3*(MM+1) + 255)/256, 256, 0, sB>>>();
    k_hist<<<(3*EE + 255)/256, 256, 0, sB>>>(ni0, ei0, ni1, ei1, ni2, ei2);
    k_scan<<<6, 1024, 0, sB>>>();
    k_scatter<<<(3*EE + 255)/256, 256, 0, sB>>>(ni0, ei0, ni1, ei1, ni2, ei2);
    cudaEventRecord(evJ, sB);

    // ---- main: weight prep, layer0, hyper1-lin, attention precompute, xs, s1(0) ----
    k_prepw<<<(4*3*32768 + 2*2*16384 + 255)/256, 256>>>(W0, Wh1, W1, Wh2, Wg, Wx);
    k_hmma<0><<<dim3(2,32,3), 256>>>(g, pWp + 0*98304, p_h, b0, 4096, 256, 256, 256,
                                     (long long)4096*256, 32768LL, (long long)4096*256, 256LL, 1, S1, IS1, 1.f);
    k_hmma<1><<<dim3(2,96,3), 256>>>(p_h, pWp + 1*98304, p_xl, nullptr, 12288, 256, 256, 256,
                                     0LL, 32768LL, (long long)12288*256, 0LL, 0, S1, IS1, 1.f);
    k_watt<<<(2*2*3*FF*32 + 255)/256, 256>>>(Wh1, at1, Wh2, at2);
    k_s2all<<<(MM*32 + 255)/256, 256>>>(hA);
    k_hmma<1><<<dim3(1,32,2), 256>>>(x, pWpc + 32768, p_xsh, bx + 128,
                                     4096, 128, 256, 128,
                                     0LL, 16384LL, (long long)4096*128, 128LL, 1, S1, IS1, 1.f);
    k_s1<<<(NN*32 + 255)/256, 256>>>(0, p_h);
    cudaStreamWaitEvent(0, evJ, 0);

    // ---- hyper1 ----
    k_stats<<<(3*NN*32 + 255)/256, 256>>>(0, hw, 1);
    k_edge<<<(3*MM*32 + 255)/256, 256>>>(0);
    k_node<<<(NN*32 + 255)/256, 256>>>(0, bc1, p_h, IS1);

    // ---- layer1 ----
    k_hmma<0><<<dim3(2,32,3), 256>>>(p_h, pWp + 2*98304, p_h2, b1, 4096, 256, 256, 256,
                                     (long long)4096*256, 32768LL, (long long)4096*256, 256LL, 1, SK, ISK, 1.f);
    k_s1<<<(NN*32 + 255)/256, 256>>>(1, p_h2);

    // ---- hyper2 ----
    k_hmma<1><<<dim3(2,96,3), 256>>>(p_h2, pWp + 3*98304, p_xl, nullptr, 12288, 256, 256, 256,
                                     0LL, 32768LL, (long long)12288*256, 0LL, 0, SK, ISK, 1024.f);
    k_stats<<<(3*NN*32 + 255)/256, 256>>>(1, hw, 0);
    k_edge<<<(3*MM*32 + 255)/256, 256>>>(1);
    k_node<<<(NN*32 + 255)/256, 256>>>(1, bc2, out + HOFF, ISK);

    // ---- new_g projection ----
    k_hmma<1><<<dim3(1,32,2), 256>>>(out + HOFF + (size_t)4096*256, pWpc + 0, p_newgh, bg + 128,
                                     4096, 128, 256, 128,
                                     (long long)4096*256, 16384LL, (long long)4096*128, 128LL, 1, SK, ISK, 1024.f);

    // ---- result ----
    k_hmma_nt<<<dim3(32,32,2), 256>>>((const __half*)p_xsh, (const __half*)p_newgh, out,
                                      4096, 4096, 128, 8192,
                                      (long long)4096*128, (long long)4096*128, 4096LL, ISK);
}

// round 16
// speedup vs baseline: 1.0662x; 1.0367x over previous
#include <cuda_runtime.h>
#include <cuda_fp16.h>
#include <math.h>

#define NN 12288
#define SS 4096
#define MM 16384
#define EE 393216
#define FF 256
#define CC 128
#define SLOPE 0.2f
#define HOFF 33554432   // 4096*8192, h output starts here

// ---------------- scratch (static device memory; no allocation) ----------------
__device__ float    g_h  [NN*FF];
__device__ float    g_h2 [NN*FF];
__device__ __half   g_xl [3][NN*FF];    // fp16 rows for gather (layer1: scaled x1024)
__device__ __half   g_m  [3][MM*FF];    // fp16 rows for gather (layer1: scaled x1024)
__device__ float    g_w1 [2][3][FF];
__device__ float    g_w2 [2][3][FF];
__device__ float    g_s1 [3][NN];
__device__ float    g_s2 [2][3][MM];
__device__ float4   g_ninfo[3][NN];     // (s1, max, 1/sum, 1/D)
__device__ float    g_Dv [3][NN];
__device__ int      g_noff[3][NN+1];
__device__ int      g_eoff[3][MM+1];
__device__ int      g_ncur[3][NN];
__device__ int      g_ecur[3][MM];
__device__ int      g_eiN [3][EE];
__device__ int      g_niE [3][EE];
__device__ __half   g_newgh[2][SS*CC];
__device__ __half   g_xsh  [2][SS*CC];
__device__ unsigned g_Wp [4][3][32768];
__device__ unsigned g_Wpc[2][2][16384];

__device__ __forceinline__ float lk(float v){ return v >= 0.f ? v : SLOPE * v; }
__device__ __forceinline__ unsigned packh2(float x, float y){
    __half2 h = __floats2half2_rn(x, y);
    return *(unsigned*)&h;
}

// ---------------- weight prep: fp32 -> packed half2 [K/2][N] ----------------
__global__ void k_prepw(const float* __restrict__ W0, const float* __restrict__ Wh1,
                        const float* __restrict__ W1, const float* __restrict__ Wh2,
                        const float* __restrict__ Wg, const float* __restrict__ Wx){
    int i = blockIdx.x * blockDim.x + threadIdx.x;
    if (i < 4*3*32768){
        int set = i / 98304;
        int r   = i % 98304;
        int z   = r / 32768;
        int off = r % 32768;
        int k2  = off >> 8, n = off & 255;
        const float* W = (set==0)?W0:(set==1)?Wh1:(set==2)?W1:Wh2;
        const float* s = W + (size_t)z*65536 + (size_t)(2*k2)*256 + n;
        g_Wp[set][z][off] = packh2(s[0], s[256]);
    } else {
        int j = i - 4*3*32768;
        if (j < 2*2*16384){
            int set = j / 32768;
            int r   = j % 32768;
            int z   = r / 16384;
            int off = r % 16384;
            int k2  = off >> 7, n = off & 127;
            const float* W = set ? Wx : Wg;
            const float* s = W + (size_t)(z+1)*32768 + (size_t)(2*k2)*128 + n;
            g_Wpc[set][z][off] = packh2(s[0], s[128]);
        }
    }
}

// ---------------- setup: counting-sort CSR build ----------------
__global__ void k_zero(){
    int i = blockIdx.x * blockDim.x + threadIdx.x;
    if (i < 3*(NN+1)) ((int*)g_noff)[i] = 0;
    if (i < 3*(MM+1)) ((int*)g_eoff)[i] = 0;
}

__global__ void k_hist(const int* __restrict__ ni0, const int* __restrict__ ei0,
                       const int* __restrict__ ni1, const int* __restrict__ ei1,
                       const int* __restrict__ ni2, const int* __restrict__ ei2){
    int idx = blockIdx.x * blockDim.x + threadIdx.x;
    if (idx >= 3*EE) return;
    int b = idx / EE, j = idx % EE;
    const int* ni = (b==0) ? ni0 : (b==1) ? ni1 : ni2;
    const int* ei = (b==0) ? ei0 : (b==1) ? ei1 : ei2;
    atomicAdd(&g_noff[b][ni[j]+1], 1);
    atomicAdd(&g_eoff[b][ei[j]+1], 1);
}

__global__ void k_scan(){
    int bid = blockIdx.x;
    int *arr, *cur; int len;
    if (bid < 3){ arr = g_noff[bid];   cur = g_ncur[bid];   len = NN+1; }
    else        { arr = g_eoff[bid-3]; cur = g_ecur[bid-3]; len = MM+1; }
    __shared__ int wsum[32];
    int lane = threadIdx.x & 31, wid = threadIdx.x >> 5;
    int carry = 0;
    for (int base = 0; base < len; base += 1024){
        int i = base + threadIdx.x;
        int v = (i < len) ? arr[i] : 0;
        int s = v;
        #pragma unroll
        for (int o = 1; o < 32; o <<= 1){
            int t = __shfl_up_sync(0xffffffffu, s, o);
            if (lane >= o) s += t;
        }
        if (lane == 31) wsum[wid] = s;
        __syncthreads();
        if (wid == 0){
            int ws = wsum[lane];
            #pragma unroll
            for (int o = 1; o < 32; o <<= 1){
                int t = __shfl_up_sync(0xffffffffu, ws, o);
                if (lane >= o) ws += t;
            }
            wsum[lane] = ws;
        }
        __syncthreads();
        int incl = s + (wid ? wsum[wid-1] : 0) + carry;
        int tot = wsum[31];
        if (i < len){ arr[i] = incl; if (i < len-1) cur[i] = incl; }
        __syncthreads();
        carry += tot;
    }
}

__global__ void k_scatter(const int* __restrict__ ni0, const int* __restrict__ ei0,
                          const int* __restrict__ ni1, const int* __restrict__ ei1,
                          const int* __restrict__ ni2, const int* __restrict__ ei2){
    int idx = blockIdx.x * blockDim.x + threadIdx.x;
    if (idx >= 3*EE) return;
    int b = idx / EE, j = idx % EE;
    const int* ni = (b==0) ? ni0 : (b==1) ? ni1 : ni2;
    const int* ei = (b==0) ? ei0 : (b==1) ? ei1 : ei2;
    int n = ni[j], e = ei[j];
    int pn = atomicAdd(&g_ncur[b][n], 1); g_eiN[b][pn] = e;
    int pe = atomicAdd(&g_ecur[b][e], 1); g_niE[b][pe] = n;
}

// ---------------- fp16 tensor-core GEMM (NN), packed-fp16 B, reg double-buffered ----------------
template<int OUTH>
__global__ void __launch_bounds__(256) k_hmma(
    const float* __restrict__ A, const unsigned* __restrict__ Bp,
    void* __restrict__ Cv, const float* __restrict__ bias,
    int M, int N, int K, int ldc,
    long long sAz, long long sBz, long long sCz, long long sbz,
    int act, float ascale, float inv_ascale, float oscale)
{
    __shared__ unsigned As2[16][136];
    __shared__ unsigned Bs2[16][136];
    int z = blockIdx.z;
    A += (size_t)z * sAz; Bp += (size_t)z * sBz;
    if (bias) bias += (size_t)z * sbz;
    int bm = blockIdx.y * 128, bn = blockIdx.x * 128;
    int tid = threadIdx.x;
    int warp = tid >> 5, lane = tid & 31;
    int wm = warp & 3, wn = warp >> 2;
    int g = lane >> 2, tg = lane & 3;

    float c[2][8][4];
    #pragma unroll
    for (int mt = 0; mt < 2; mt++)
        #pragma unroll
        for (int nt = 0; nt < 8; nt++)
            #pragma unroll
            for (int i = 0; i < 4; i++) c[mt][nt][i] = 0.f;

    float4 va[4]; uint4 vb[2];
    #pragma unroll
    for (int i = 0; i < 4; i++){
        int q = tid + 256*i;
        int r = q >> 3, cc = (q & 7) << 2;
        va[i] = *(const float4*)(A + (size_t)(bm + r) * K + cc);
    }
    #pragma unroll
    for (int i = 0; i < 2; i++){
        int q = tid + 256*i;
        int row = q >> 5, c4 = q & 31;
        vb[i] = *(const uint4*)(Bp + (size_t)row * N + bn + c4*4);
    }

    for (int kt = 0; kt < K; kt += 32){
        #pragma unroll
        for (int i = 0; i < 4; i++){
            int q = tid + 256*i;
            int r = q >> 3, cc = (q & 7) << 2;
            As2[(cc>>1)  ][r] = packh2(va[i].x*ascale, va[i].y*ascale);
            As2[(cc>>1)+1][r] = packh2(va[i].z*ascale, va[i].w*ascale);
        }
        #pragma unroll
        for (int i = 0; i < 2; i++){
            int q = tid + 256*i;
            int row = q >> 5, c4 = q & 31;
            *(uint4*)&Bs2[row][c4*4] = vb[i];
        }
        __syncthreads();
        if (kt + 32 < K){
            #pragma unroll
            for (int i = 0; i < 4; i++){
                int q = tid + 256*i;
                int r = q >> 3, cc = (q & 7) << 2;
                va[i] = *(const float4*)(A + (size_t)(bm + r) * K + kt + 32 + cc);
            }
            #pragma unroll
            for (int i = 0; i < 2; i++){
                int q = tid + 256*i;
                int row = q >> 5, c4 = q & 31;
                vb[i] = *(const uint4*)(Bp + (size_t)((kt >> 1) + 16 + row) * N + bn + c4*4);
            }
        }

        #pragma unroll
        for (int s = 0; s < 2; s++){
            int s8 = s * 8;
            unsigned bf[8][2];
            #pragma unroll
            for (int nt = 0; nt < 8; nt++){
                int col = wn*64 + nt*8 + g;
                bf[nt][0] = Bs2[s8+tg  ][col];
                bf[nt][1] = Bs2[s8+tg+4][col];
            }
            #pragma unroll
            for (int mt = 0; mt < 2; mt++){
                int mb = wm*32 + mt*16;
                unsigned a0 = As2[s8+tg  ][mb+g];
                unsigned a1 = As2[s8+tg  ][mb+8+g];
                unsigned a2 = As2[s8+tg+4][mb+g];
                unsigned a3 = As2[s8+tg+4][mb+8+g];
                #pragma unroll
                for (int nt = 0; nt < 8; nt++){
                    asm volatile(
                        "mma.sync.aligned.m16n8k16.row.col.f32.f16.f16.f32 "
                        "{%0,%1,%2,%3}, {%4,%5,%6,%7}, {%8,%9}, {%0,%1,%2,%3};"
                        : "+f"(c[mt][nt][0]), "+f"(c[mt][nt][1]),
                          "+f"(c[mt][nt][2]), "+f"(c[mt][nt][3])
                        : "r"(a0), "r"(a1), "r"(a2), "r"(a3),
                          "r"(bf[nt][0]), "r"(bf[nt][1]));
                }
            }
        }
        __syncthreads();
    }

    #pragma unroll
    for (int mt = 0; mt < 2; mt++){
        int row0 = bm + wm*32 + mt*16 + g;
        #pragma unroll
        for (int nt = 0; nt < 8; nt++){
            int col = bn + wn*64 + nt*8 + 2*tg;
            float b0 = 0.f, b1 = 0.f;
            if (bias){ b0 = bias[col]; b1 = bias[col+1]; }
            float2 v0, v1;
            v0.x = c[mt][nt][0]*inv_ascale + b0; v0.y = c[mt][nt][1]*inv_ascale + b1;
            v1.x = c[mt][nt][2]*inv_ascale + b0; v1.y = c[mt][nt][3]*inv_ascale + b1;
            if (act){ v0.x = lk(v0.x); v0.y = lk(v0.y); v1.x = lk(v1.x); v1.y = lk(v1.y); }
            if (OUTH){
                __half* C = (__half*)Cv + (size_t)blockIdx.z * sCz;
                *(__half2*)(C + (size_t)row0 * ldc + col)       = __floats2half2_rn(v0.x*oscale, v0.y*oscale);
                *(__half2*)(C + (size_t)(row0 + 8) * ldc + col) = __floats2half2_rn(v1.x*oscale, v1.y*oscale);
            } else {
                float* C = (float*)Cv + (size_t)blockIdx.z * sCz;
                *(float2*)(C + (size_t)row0 * ldc + col)       = v0;
                *(float2*)(C + (size_t)(row0 + 8) * ldc + col) = v1;
            }
        }
    }
}

// ---------------- fp16-input NT GEMM: C = (A[M,K] @ B[N,K]^T) * oscale ----------------
__global__ void __launch_bounds__(256) k_hmma_nt(
    const __half* __restrict__ A, const __half* __restrict__ B,
    float* __restrict__ C, int M, int N, int K, int ldc,
    long long sAz, long long sBz, long long sCz, float oscale)
{
    __shared__ unsigned As2[16][136];
    __shared__ unsigned Bs2[16][136];
    int z = blockIdx.z;
    A += (size_t)z * sAz; B += (size_t)z * sBz; C += (size_t)z * sCz;
    int bm = blockIdx.y * 128, bn = blockIdx.x * 128;
    int tid = threadIdx.x;
    int warp = tid >> 5, lane = tid & 31;
    int wm = warp & 3, wn = warp >> 2;
    int g = lane >> 2, tg = lane & 3;

    float c[2][8][4];
    #pragma unroll
    for (int mt = 0; mt < 2; mt++)
        #pragma unroll
        for (int nt = 0; nt < 8; nt++)
            #pragma unroll
            for (int i = 0; i < 4; i++) c[mt][nt][i] = 0.f;

    float4 va[2], vb[2];
    #pragma unroll
    for (int i = 0; i < 2; i++){
        int q = tid + 256*i;
        int r = q >> 2, cc = (q & 3) << 3;
        va[i] = *(const float4*)(A + (size_t)(bm + r) * K + cc);
        vb[i] = *(const float4*)(B + (size_t)(bn + r) * K + cc);
    }

    for (int kt = 0; kt < K; kt += 32){
        #pragma unroll
        for (int i = 0; i < 2; i++){
            int q = tid + 256*i;
            int r = q >> 2, cc = (q & 3) << 3;
            const unsigned* pa = (const unsigned*)&va[i];
            const unsigned* pb = (const unsigned*)&vb[i];
            int kh = cc >> 1;
            As2[kh  ][r] = pa[0]; As2[kh+1][r] = pa[1];
            As2[kh+2][r] = pa[2]; As2[kh+3][r] = pa[3];
            Bs2[kh  ][r] = pb[0]; Bs2[kh+1][r] = pb[1];
            Bs2[kh+2][r] = pb[2]; Bs2[kh+3][r] = pb[3];
        }
        __syncthreads();
        if (kt + 32 < K){
            #pragma unroll
            for (int i = 0; i < 2; i++){
                int q = tid + 256*i;
                int r = q >> 2, cc = (q & 3) << 3;
                va[i] = *(const float4*)(A + (size_t)(bm + r) * K + kt + 32 + cc);
                vb[i] = *(const float4*)(B + (size_t)(bn + r) * K + kt + 32 + cc);
            }
        }

        #pragma unroll
        for (int s = 0; s < 2; s++){
            int s8 = s * 8;
            unsigned bf[8][2];
            #pragma unroll
            for (int nt = 0; nt < 8; nt++){
                int col = wn*64 + nt*8 + g;
                bf[nt][0] = Bs2[s8+tg  ][col];
                bf[nt][1] = Bs2[s8+tg+4][col];
            }
            #pragma unroll
            for (int mt = 0; mt < 2; mt++){
                int mb = wm*32 + mt*16;
                unsigned a0 = As2[s8+tg  ][mb+g];
                unsigned a1 = As2[s8+tg  ][mb+8+g];
                unsigned a2 = As2[s8+tg+4][mb+g];
                unsigned a3 = As2[s8+tg+4][mb+8+g];
                #pragma unroll
                for (int nt = 0; nt < 8; nt++){
                    asm volatile(
                        "mma.sync.aligned.m16n8k16.row.col.f32.f16.f16.f32 "
                        "{%0,%1,%2,%3}, {%4,%5,%6,%7}, {%8,%9}, {%0,%1,%2,%3};"
                        : "+f"(c[mt][nt][0]), "+f"(c[mt][nt][1]),
                          "+f"(c[mt][nt][2]), "+f"(c[mt][nt][3])
                        : "r"(a0), "r"(a1), "r"(a2), "r"(a3),
                          "r"(bf[nt][0]), "r"(bf[nt][1]));
                }
            }
        }
        __syncthreads();
    }

    #pragma unroll
    for (int mt = 0; mt < 2; mt++){
        int row0 = bm + wm*32 + mt*16 + g;
        #pragma unroll
        for (int nt = 0; nt < 8; nt++){
            int col = bn + wn*64 + nt*8 + 2*tg;
            float2 v0, v1;
            v0.x = c[mt][nt][0]*oscale; v0.y = c[mt][nt][1]*oscale;
            v1.x = c[mt][nt][2]*oscale; v1.y = c[mt][nt][3]*oscale;
            __stcs((float2*)(C + (size_t)row0 * ldc + col), v0);
            __stcs((float2*)(C + (size_t)(row0 + 8) * ldc + col), v1);
        }
    }
}

// ---------------- w1/w2: Wh_l[b] @ att halves (both layers) ----------------
__global__ void k_watt(const float* __restrict__ Wh1, const float* __restrict__ at1,
                       const float* __restrict__ Wh2, const float* __restrict__ at2){
    int w = (blockIdx.x * blockDim.x + threadIdx.x) >> 5;
    int lane = threadIdx.x & 31;
    if (w >= 2*2*3*FF) return;
    int l    = w / (2*3*FF);
    int half = (w / (3*FF)) % 2;
    int b    = (w / FF) % 3, k = w % FF;
    const float* Wh  = l ? Wh2 : Wh1;
    const float* att = l ? at2 : at1;
    const float* row = Wh + (size_t)b*FF*FF + (size_t)k*FF;
    const float* av  = att + b*512 + half*256;
    float4 r0 = ((const float4*)row)[lane*2], r1 = ((const float4*)row)[lane*2+1];
    float4 a0 = ((const float4*)av )[lane*2], a1 = ((const float4*)av )[lane*2+1];
    float s = r0.x*a0.x + r0.y*a0.y + r0.z*a0.z + r0.w*a0.w
            + r1.x*a1.x + r1.y*a1.y + r1.z*a1.z + r1.w*a1.w;
    #pragma unroll
    for (int o = 16; o; o >>= 1) s += __shfl_xor_sync(0xffffffffu, s, o);
    if (lane == 0){
        if (half) g_w2[l][b][k] = s;
        else      g_w1[l][b][k] = s;
    }
}

// ---------------- s2[l][b][e] = hA[e] . w2[l][b] ----------------
__global__ void k_s2all(const float* __restrict__ hA){
    int w = (blockIdx.x * blockDim.x + threadIdx.x) >> 5;
    int lane = threadIdx.x & 31;
    if (w >= MM) return;
    int e = w;
    const float* row = hA + (size_t)e*FF;
    float4 r0 = ((const float4*)row)[lane*2], r1 = ((const float4*)row)[lane*2+1];
    #pragma unroll
    for (int q = 0; q < 6; q++){
        const float* w2 = g_w2[q/3][q%3];
        float4 a0 = ((const float4*)w2)[lane*2], a1 = ((const float4*)w2)[lane*2+1];
        float s = r0.x*a0.x + r0.y*a0.y + r0.z*a0.z + r0.w*a0.w
                + r1.x*a1.x + r1.y*a1.y + r1.z*a1.z + r1.w*a1.w;
        #pragma unroll
        for (int o = 16; o; o >>= 1) s += __shfl_xor_sync(0xffffffffu, s, o);
        if (lane == 0) g_s2[q/3][q%3][e] = s;
    }
}

// ---------------- s1[b][n] = h[n] . w1[l][b] ----------------
__global__ void k_s1(int l, const float* __restrict__ hsrc){
    int w = (blockIdx.x * blockDim.x + threadIdx.x) >> 5;
    int lane = threadIdx.x & 31;
    if (w >= NN) return;
    int n = w;
    const float4* hr = (const float4*)(hsrc + (size_t)n*FF);
    float4 v0 = hr[lane], v1 = hr[32+lane];
    #pragma unroll
    for (int b = 0; b < 3; b++){
        const float* w1 = g_w1[l][b];
        float4 a0 = ((const float4*)w1)[lane], a1 = ((const float4*)w1)[32+lane];
        float s = v0.x*a0.x + v0.y*a0.y + v0.z*a0.z + v0.w*a0.w
                + v1.x*a1.x + v1.y*a1.y + v1.z*a1.z + v1.w*a1.w;
        #pragma unroll
        for (int o = 16; o; o >>= 1) s += __shfl_xor_sync(0xffffffffu, s, o);
        if (lane == 0) g_s1[b][n] = s;
    }
}

// ---------------- stats: single-pass online softmax (+ D on layer 0) -> ninfo ----------------
__global__ void k_stats(int l, const float* __restrict__ hw, int computeD){
    int w = (blockIdx.x * blockDim.x + threadIdx.x) >> 5;
    int lane = threadIdx.x & 31;
    if (w >= 3*NN) return;
    int b = w / NN, n = w % NN;

    float s1n = g_s1[b][n];
    const float* s2b = g_s2[l][b];
    int beg = g_noff[b][n], end = g_noff[b][n+1];

    float mx = -1e30f, sum = 0.f, ds = 0.f;
    for (int p = beg + lane; p < end; p += 32){
        int e = __ldcs(&g_eiN[b][p]);
        float a = lk(s1n + s2b[e]);
        if (computeD) ds += hw[e];
        float mo = mx;
        mx = fmaxf(mx, a);
        sum = sum * __expf(mo - mx) + __expf(a - mx);
    }
    #pragma unroll
    for (int o = 16; o; o >>= 1){
        float mo2 = __shfl_xor_sync(0xffffffffu, mx, o);
        float so2 = __shfl_xor_sync(0xffffffffu, sum, o);
        float mn = fmaxf(mx, mo2);
        sum = sum * __expf(mx - mn) + so2 * __expf(mo2 - mn);
        mx = mn;
        if (computeD) ds += __shfl_xor_sync(0xffffffffu, ds, o);
    }
    if (lane == 0){
        float di;
        if (computeD){
            di = (ds > 0.f) ? 1.f/ds : 0.f;
            g_Dv[b][n] = di;
        } else {
            di = g_Dv[b][n];
        }
        if (end > beg) g_ninfo[b][n] = make_float4(s1n, mx, 1.f/sum, di);
        else           g_ninfo[b][n] = make_float4(s1n, 0.f, 0.f, 0.f);
    }
}

// ---------------- gather helper: accumulate one row into acc[8] ----------------
__device__ __forceinline__ void row_acc(const __half* base, int r, int lane, float c, float* acc){
    float4 raw = *(const float4*)(base + (size_t)r * FF + lane*8);
    const __half2* hp = (const __half2*)&raw;
    #pragma unroll
    for (int q = 0; q < 4; q++){
        float2 f = __half22float2(hp[q]);
        acc[2*q]   += c*f.x;
        acc[2*q+1] += c*f.y;
    }
}

// ---------------- edge pass: 4-way unrolled gather ----------------
__global__ void k_edge(int l){
    int w = (blockIdx.x * blockDim.x + threadIdx.x) >> 5;
    int lane = threadIdx.x & 31;
    if (w >= 3*MM) return;
    int b = w / MM, e = w % MM;
    int beg = g_eoff[b][e], end = g_eoff[b][e+1];
    float s2e = g_s2[l][b][e];
    const __half* xlb = g_xl[b];
    float acc[8] = {0,0,0,0,0,0,0,0};
    for (int base = beg; base < end; base += 32){
        int p = base + lane;
        int nrow = 0; float coef = 0.f;
        if (p < end){
            nrow = __ldcs(&g_niE[b][p]);
            float4 info = g_ninfo[b][nrow];
            coef = __expf(lk(info.x + s2e) - info.y) * info.z;
        }
        int cnt = min(32, end - base);
        int t = 0;
        for (; t + 4 <= cnt; t += 4){
            int   r0 = __shfl_sync(0xffffffffu, nrow, t);
            float c0 = __shfl_sync(0xffffffffu, coef, t);
            int   r1 = __shfl_sync(0xffffffffu, nrow, t+1);
            float c1 = __shfl_sync(0xffffffffu, coef, t+1);
            int   r2 = __shfl_sync(0xffffffffu, nrow, t+2);
            float c2 = __shfl_sync(0xffffffffu, coef, t+2);
            int   r3 = __shfl_sync(0xffffffffu, nrow, t+3);
            float c3 = __shfl_sync(0xffffffffu, coef, t+3);
            float4 raw0 = *(const float4*)(xlb + (size_t)r0 * FF + lane*8);
            float4 raw1 = *(const float4*)(xlb + (size_t)r1 * FF + lane*8);
            float4 raw2 = *(const float4*)(xlb + (size_t)r2 * FF + lane*8);
            float4 raw3 = *(const float4*)(xlb + (size_t)r3 * FF + lane*8);
            const __half2* h0 = (const __half2*)&raw0;
            const __half2* h1 = (const __half2*)&raw1;
            const __half2* h2 = (const __half2*)&raw2;
            const __half2* h3 = (const __half2*)&raw3;
            #pragma unroll
            for (int q = 0; q < 4; q++){
                float2 f0 = __half22float2(h0[q]);
                float2 f1 = __half22float2(h1[q]);
                float2 f2 = __half22float2(h2[q]);
                float2 f3 = __half22float2(h3[q]);
                acc[2*q]   += c0*f0.x + c1*f1.x + c2*f2.x + c3*f3.x;
                acc[2*q+1] += c0*f0.y + c1*f1.y + c2*f2.y + c3*f3.y;
            }
        }
        for (; t < cnt; t++){
            int   r0 = __shfl_sync(0xffffffffu, nrow, t);
            float c0 = __shfl_sync(0xffffffffu, coef, t);
            row_acc(xlb, r0, lane, c0, acc);
        }
    }
    int ce = end - beg;
    float bi = (ce > 0) ? 1.f/(float)ce : 0.f;
    __half2 o[4];
    o[0] = __floats2half2_rn(bi*acc[0], bi*acc[1]);
    o[1] = __floats2half2_rn(bi*acc[2], bi*acc[3]);
    o[2] = __floats2half2_rn(bi*acc[4], bi*acc[5]);
    o[3] = __floats2half2_rn(bi*acc[6], bi*acc[7]);
    *(float4*)(g_m[b] + (size_t)e * FF + lane*8) = *(float4*)o;
}

// ---------------- node pass: 4-way unrolled ----------------
__global__ void k_node(int l, const float* __restrict__ bc, float* __restrict__ hout, float invS){
    int w = (blockIdx.x * blockDim.x + threadIdx.x) >> 5;
    int lane = threadIdx.x & 31;
    if (w >= NN) return;
    int n = w;
    float t[8] = {0,0,0,0,0,0,0,0};
    #pragma unroll
    for (int b = 0; b < 3; b++){
        int beg = g_noff[b][n], end = g_noff[b][n+1];
        float4 info = g_ninfo[b][n];
        float s1n = info.x, mxn = info.y, rsn = info.z, di = info.w;
        const float* s2b = g_s2[l][b];
        const __half* mb = g_m[b];
        float a[8] = {0,0,0,0,0,0,0,0};
        for (int base = beg; base < end; base += 32){
            int p = base + lane;
            int er = 0; float coef = 0.f;
            if (p < end){
                er = __ldcs(&g_eiN[b][p]);
                coef = __expf(lk(s1n + s2b[er]) - mxn) * rsn;
            }
            int cnt = min(32, end - base);
            int t2 = 0;
            for (; t2 + 4 <= cnt; t2 += 4){
                int   r0 = __shfl_sync(0xffffffffu, er, t2);
                float c0 = __shfl_sync(0xffffffffu, coef, t2);
                int   r1 = __shfl_sync(0xffffffffu, er, t2+1);
                float c1 = __shfl_sync(0xffffffffu, coef, t2+1);
                int   r2 = __shfl_sync(0xffffffffu, er, t2+2);
                float c2 = __shfl_sync(0xffffffffu, coef, t2+2);
                int   r3 = __shfl_sync(0xffffffffu, er, t2+3);
                float c3 = __shfl_sync(0xffffffffu, coef, t2+3);
                float4 raw0 = *(const float4*)(mb + (size_t)r0 * FF + lane*8);
                float4 raw1 = *(const float4*)(mb + (size_t)r1 * FF + lane*8);
                float4 raw2 = *(const float4*)(mb + (size_t)r2 * FF + lane*8);
                float4 raw3 = *(const float4*)(mb + (size_t)r3 * FF + lane*8);
                const __half2* h0 = (const __half2*)&raw0;
                const __half2* h1 = (const __half2*)&raw1;
                const __half2* h2 = (const __half2*)&raw2;
                const __half2* h3 = (const __half2*)&raw3;
                #pragma unroll
                for (int q = 0; q < 4; q++){
                    float2 f0 = __half22float2(h0[q]);
                    float2 f1 = __half22float2(h1[q]);
                    float2 f2 = __half22float2(h2[q]);
                    float2 f3 = __half22float2(h3[q]);
                    a[2*q]   += c0*f0.x + c1*f1.x + c2*f2.x + c3*f3.x;
                    a[2*q+1] += c0*f0.y + c1*f1.y + c2*f2.y + c3*f3.y;
                }
            }
            for (; t2 < cnt; t2++){
                int   r0 = __shfl_sync(0xffffffffu, er, t2);
                float c0 = __shfl_sync(0xffffffffu, coef, t2);
                row_acc(mb, r0, lane, c0, a);
            }
        }
        #pragma unroll
        for (int i = 0; i < 8; i++) t[i] += di * a[i];
    }
    #pragma unroll
    for (int i = 0; i < 8; i++) t[i] *= invS;
    #pragma unroll
    for (int k = 0; k < 3; k++){
        float4 b0 = *(const float4*)(bc + k*256 + lane*8);
        float4 b1 = *(const float4*)(bc + k*256 + lane*8 + 4);
        t[0] += b0.x; t[1] += b0.y; t[2] += b0.z; t[3] += b0.w;
        t[4] += b1.x; t[5] += b1.y; t[6] += b1.z; t[7] += b1.w;
    }
    #pragma unroll
    for (int i = 0; i < 8; i++) t[i] = lk(t[i]);
    *(float4*)(hout + (size_t)n * FF + lane*8)     = make_float4(t[0], t[1], t[2], t[3]);
    *(float4*)(hout + (size_t)n * FF + lane*8 + 4) = make_float4(t[4], t[5], t[6], t[7]);
}

// ---------------- host launcher ----------------
static void* symaddr(const void* sym){ void* p = nullptr; cudaGetSymbolAddress(&p, sym); return p; }

extern "C" void kernel_launch(void* const* d_in, const int* in_sizes, int n_in,
                              void* d_out, int out_size){
    const float* g   = (const float*)d_in[0];
    const float* x   = (const float*)d_in[1];
    const float* hw  = (const float*)d_in[2];
    const float* hA  = (const float*)d_in[3];
    const int* ni0 = (const int*)d_in[4]; const int* ei0 = (const int*)d_in[5];
    const int* ni1 = (const int*)d_in[6]; const int* ei1 = (const int*)d_in[7];
    const int* ni2 = (const int*)d_in[8]; const int* ei2 = (const int*)d_in[9];
    const float* W0  = (const float*)d_in[10]; const float* b0  = (const float*)d_in[11];
    const float* Wh1 = (const float*)d_in[12]; const float* at1 = (const float*)d_in[13];
    const float* bc1 = (const float*)d_in[14];
    const float* W1  = (const float*)d_in[15]; const float* b1  = (const float*)d_in[16];
    const float* Wh2 = (const float*)d_in[17]; const float* at2 = (const float*)d_in[18];
    const float* bc2 = (const float*)d_in[19];
    const float* Wg  = (const float*)d_in[20]; const float* bg  = (const float*)d_in[21];
    const float* Wx  = (const float*)d_in[22]; const float* bx  = (const float*)d_in[23];
    float* out = (float*)d_out;

    float*    p_h     = (float*)symaddr(g_h);
    float*    p_h2    = (float*)symaddr(g_h2);
    void*     p_xl    = symaddr(g_xl);
    void*     p_newgh = symaddr(g_newgh);
    void*     p_xsh   = symaddr(g_xsh);
    const unsigned* pWp  = (const unsigned*)symaddr(g_Wp);
    const unsigned* pWpc = (const unsigned*)symaddr(g_Wpc);

    const float S1 = 1.f,    IS1 = 1.f;
    const float SK = 1024.f, ISK = 1.f/1024.f;

    cudaStream_t sB = 0;
    cudaEvent_t evF = 0, evJ = 0, evL1 = 0, evS1 = 0;
    cudaStreamCreateWithFlags(&sB, cudaStreamNonBlocking);
    cudaEventCreateWithFlags(&evF,  cudaEventDisableTiming);
    cudaEventCreateWithFlags(&evJ,  cudaEventDisableTiming);
    cudaEventCreateWithFlags(&evL1, cudaEventDisableTiming);
    cudaEventCreateWithFlags(&evS1, cudaEventDisableTiming);

    cudaEventRecord(evF, 0);
    cudaStreamWaitEvent(sB, evF, 0);

    // ---- side stream: CSR build ----
    k_zero<<<(3*(MM+1) + 255)/256, 256, 0, sB>>>();
    k_hist<<<(3*EE + 255)/256, 256, 0, sB>>>(ni0, ei0, ni1, ei1, ni2, ei2);
    k_scan<<<6, 1024, 0, sB>>>();
    k_scatter<<<(3*EE + 255)/256, 256, 0, sB>>>(ni0, ei0, ni1, ei1, ni2, ei2);
    cudaEventRecord(evJ, sB);

    // ---- main: weight prep, layer0, hyper1-lin, attention precompute, xs, s1(0) ----
    k_prepw<<<(4*3*32768 + 2*2*16384 + 255)/256, 256>>>(W0, Wh1, W1, Wh2, Wg, Wx);
    k_hmma<0><<<dim3(2,32,3), 256>>>(g, pWp + 0*98304, p_h, b0, 4096, 256, 256, 256,
                                     (long long)4096*256, 32768LL, (long long)4096*256, 256LL, 1, S1, IS1, 1.f);
    k_hmma<1><<<dim3(2,96,3), 256>>>(p_h, pWp + 1*98304, p_xl, nullptr, 12288, 256, 256, 256,
                                     0LL, 32768LL, (long long)12288*256, 0LL, 0, S1, IS1, 1.f);
    k_watt<<<(2*2*3*FF*32 + 255)/256, 256>>>(Wh1, at1, Wh2, at2);
    k_s2all<<<(MM*32 + 255)/256, 256>>>(hA);
    k_hmma<1><<<dim3(1,32,2), 256>>>(x, pWpc + 32768, p_xsh, bx + 128,
                                     4096, 128, 256, 128,
                                     0LL, 16384LL, (long long)4096*128, 128LL, 1, S1, IS1, 1.f);
    k_s1<<<(NN*32 + 255)/256, 256>>>(0, p_h);
    cudaStreamWaitEvent(0, evJ, 0);

    // ---- hyper1 ----
    k_stats<<<(3*NN*32 + 255)/256, 256>>>(0, hw, 1);
    k_edge<<<(3*MM*32 + 255)/256, 256>>>(0);
    k_node<<<(NN*32 + 255)/256, 256>>>(0, bc1, p_h, IS1);

    // ---- layer1 ----
    k_hmma<0><<<dim3(2,32,3), 256>>>(p_h, pWp + 2*98304, p_h2, b1, 4096, 256, 256, 256,
                                     (long long)4096*256, 32768LL, (long long)4096*256, 256LL, 1, SK, ISK, 1.f);
    cudaEventRecord(evL1, 0);

    // ---- side stream (idle after CSR): s1(1) overlapped with hyper2-lin GEMM ----
    cudaStreamWaitEvent(sB, evL1, 0);
    k_s1<<<(NN*32 + 255)/256, 256, 0, sB>>>(1, p_h2);
    cudaEventRecord(evS1, sB);

    // ---- hyper2 (main runs lin GEMM concurrently with side's s1) ----
    k_hmma<1><<<dim3(2,96,3), 256>>>(p_h2, pWp + 3*98304, p_xl, nullptr, 12288, 256, 256, 256,
                                     0LL, 32768LL, (long long)12288*256, 0LL, 0, SK, ISK, 1024.f);
    cudaStreamWaitEvent(0, evS1, 0);
    k_stats<<<(3*NN*32 + 255)/256, 256>>>(1, hw, 0);
    k_edge<<<(3*MM*32 + 255)/256, 256>>>(1);
    k_node<<<(NN*32 + 255)/256, 256>>>(1, bc2, out + HOFF, ISK);

    // ---- new_g projection ----
    k_hmma<1><<<dim3(1,32,2), 256>>>(out + HOFF + (size_t)4096*256, pWpc + 0, p_newgh, bg + 128,
                                     4096, 128, 256, 128,
                                     (long long)4096*256, 16384LL, (long long)4096*128, 128LL, 1, SK, ISK, 1024.f);

    // ---- result ----
    k_hmma_nt<<<dim3(32,32,2), 256>>>((const __half*)p_xsh, (const __half*)p_newgh, out,
                                      4096, 4096, 128, 8192,
                                      (long long)4096*128, (long long)4096*128, 4096LL, ISK);
}

// round 17
// speedup vs baseline: 1.0672x; 1.0009x over previous
#include <cuda_runtime.h>
#include <cuda_fp16.h>
#include <math.h>

#define NN 12288
#define SS 4096
#define MM 16384
#define EE 393216
#define FF 256
#define CC 128
#define SLOPE 0.2f
#define HOFF 33554432   // 4096*8192, h output starts here

// ---------------- scratch (static device memory; no allocation) ----------------
__device__ float    g_h  [NN*FF];
__device__ float    g_h2 [NN*FF];
__device__ __half   g_xl [3][NN*FF];    // fp16 rows for gather (layer1: scaled x1024)
__device__ __half   g_m  [3][MM*FF];    // fp16 rows for gather (layer1: scaled x1024)
__device__ float    g_w1 [2][3][FF];
__device__ float    g_w2 [2][3][FF];
__device__ float    g_s1 [3][NN];
__device__ float    g_s2 [2][3][MM];
__device__ float4   g_ninfo[3][NN];     // (s1, max, 1/sum, 1/D)
__device__ float    g_Dv [3][NN];
__device__ int      g_noff[3][NN+1];
__device__ int      g_eoff[3][MM+1];
__device__ int      g_ncur[3][NN];
__device__ int      g_ecur[3][MM];
__device__ int      g_eiN [3][EE];
__device__ int      g_niE [3][EE];
__device__ __half   g_newgh[2][SS*CC];
__device__ __half   g_xsh  [2][SS*CC];
__device__ unsigned g_Wp [4][3][32768];
__device__ unsigned g_Wpc[2][2][16384];

__device__ __forceinline__ float lk(float v){ return v >= 0.f ? v : SLOPE * v; }
__device__ __forceinline__ unsigned packh2(float x, float y){
    __half2 h = __floats2half2_rn(x, y);
    return *(unsigned*)&h;
}

// ---------------- weight prep: fp32 -> packed half2 [K/2][N] ----------------
__global__ void k_prepw(const float* __restrict__ W0, const float* __restrict__ Wh1,
                        const float* __restrict__ W1, const float* __restrict__ Wh2,
                        const float* __restrict__ Wg, const float* __restrict__ Wx){
    int i = blockIdx.x * blockDim.x + threadIdx.x;
    if (i < 4*3*32768){
        int set = i / 98304;
        int r   = i % 98304;
        int z   = r / 32768;
        int off = r % 32768;
        int k2  = off >> 8, n = off & 255;
        const float* W = (set==0)?W0:(set==1)?Wh1:(set==2)?W1:Wh2;
        const float* s = W + (size_t)z*65536 + (size_t)(2*k2)*256 + n;
        g_Wp[set][z][off] = packh2(s[0], s[256]);
    } else {
        int j = i - 4*3*32768;
        if (j < 2*2*16384){
            int set = j / 32768;
            int r   = j % 32768;
            int z   = r / 16384;
            int off = r % 16384;
            int k2  = off >> 7, n = off & 127;
            const float* W = set ? Wx : Wg;
            const float* s = W + (size_t)(z+1)*32768 + (size_t)(2*k2)*128 + n;
            g_Wpc[set][z][off] = packh2(s[0], s[128]);
        }
    }
}

// ---------------- setup: counting-sort CSR build ----------------
__global__ void k_zero(){
    int i = blockIdx.x * blockDim.x + threadIdx.x;
    if (i < 3*(NN+1)) ((int*)g_noff)[i] = 0;
    if (i < 3*(MM+1)) ((int*)g_eoff)[i] = 0;
}

__global__ void k_hist(const int* __restrict__ ni0, const int* __restrict__ ei0,
                       const int* __restrict__ ni1, const int* __restrict__ ei1,
                       const int* __restrict__ ni2, const int* __restrict__ ei2){
    int idx = blockIdx.x * blockDim.x + threadIdx.x;
    if (idx >= 3*EE) return;
    int b = idx / EE, j = idx % EE;
    const int* ni = (b==0) ? ni0 : (b==1) ? ni1 : ni2;
    const int* ei = (b==0) ? ei0 : (b==1) ? ei1 : ei2;
    atomicAdd(&g_noff[b][ni[j]+1], 1);
    atomicAdd(&g_eoff[b][ei[j]+1], 1);
}

__global__ void k_scan(){
    int bid = blockIdx.x;
    int *arr, *cur; int len;
    if (bid < 3){ arr = g_noff[bid];   cur = g_ncur[bid];   len = NN+1; }
    else        { arr = g_eoff[bid-3]; cur = g_ecur[bid-3]; len = MM+1; }
    __shared__ int wsum[32];
    int lane = threadIdx.x & 31, wid = threadIdx.x >> 5;
    int carry = 0;
    for (int base = 0; base < len; base += 1024){
        int i = base + threadIdx.x;
        int v = (i < len) ? arr[i] : 0;
        int s = v;
        #pragma unroll
        for (int o = 1; o < 32; o <<= 1){
            int t = __shfl_up_sync(0xffffffffu, s, o);
            if (lane >= o) s += t;
        }
        if (lane == 31) wsum[wid] = s;
        __syncthreads();
        if (wid == 0){
            int ws = wsum[lane];
            #pragma unroll
            for (int o = 1; o < 32; o <<= 1){
                int t = __shfl_up_sync(0xffffffffu, ws, o);
                if (lane >= o) ws += t;
            }
            wsum[lane] = ws;
        }
        __syncthreads();
        int incl = s + (wid ? wsum[wid-1] : 0) + carry;
        int tot = wsum[31];
        if (i < len){ arr[i] = incl; if (i < len-1) cur[i] = incl; }
        __syncthreads();
        carry += tot;
    }
}

__global__ void k_scatter(const int* __restrict__ ni0, const int* __restrict__ ei0,
                          const int* __restrict__ ni1, const int* __restrict__ ei1,
                          const int* __restrict__ ni2, const int* __restrict__ ei2){
    int idx = blockIdx.x * blockDim.x + threadIdx.x;
    if (idx >= 3*EE) return;
    int b = idx / EE, j = idx % EE;
    const int* ni = (b==0) ? ni0 : (b==1) ? ni1 : ni2;
    const int* ei = (b==0) ? ei0 : (b==1) ? ei1 : ei2;
    int n = ni[j], e = ei[j];
    int pn = atomicAdd(&g_ncur[b][n], 1); g_eiN[b][pn] = e;
    int pe = atomicAdd(&g_ecur[b][e], 1); g_niE[b][pe] = n;
}

// ---------------- fp16 tensor-core GEMM (NN), packed-fp16 B, reg double-buffered ----------------
template<int OUTH>
__global__ void __launch_bounds__(256) k_hmma(
    const float* __restrict__ A, const unsigned* __restrict__ Bp,
    void* __restrict__ Cv, const float* __restrict__ bias,
    int M, int N, int K, int ldc,
    long long sAz, long long sBz, long long sCz, long long sbz,
    int act, float ascale, float inv_ascale, float oscale)
{
    __shared__ unsigned As2[16][136];
    __shared__ unsigned Bs2[16][136];
    int z = blockIdx.z;
    A += (size_t)z * sAz; Bp += (size_t)z * sBz;
    if (bias) bias += (size_t)z * sbz;
    int bm = blockIdx.y * 128, bn = blockIdx.x * 128;
    int tid = threadIdx.x;
    int warp = tid >> 5, lane = tid & 31;
    int wm = warp & 3, wn = warp >> 2;
    int g = lane >> 2, tg = lane & 3;

    float c[2][8][4];
    #pragma unroll
    for (int mt = 0; mt < 2; mt++)
        #pragma unroll
        for (int nt = 0; nt < 8; nt++)
            #pragma unroll
            for (int i = 0; i < 4; i++) c[mt][nt][i] = 0.f;

    float4 va[4]; uint4 vb[2];
    #pragma unroll
    for (int i = 0; i < 4; i++){
        int q = tid + 256*i;
        int r = q >> 3, cc = (q & 7) << 2;
        va[i] = *(const float4*)(A + (size_t)(bm + r) * K + cc);
    }
    #pragma unroll
    for (int i = 0; i < 2; i++){
        int q = tid + 256*i;
        int row = q >> 5, c4 = q & 31;
        vb[i] = *(const uint4*)(Bp + (size_t)row * N + bn + c4*4);
    }

    for (int kt = 0; kt < K; kt += 32){
        #pragma unroll
        for (int i = 0; i < 4; i++){
            int q = tid + 256*i;
            int r = q >> 3, cc = (q & 7) << 2;
            As2[(cc>>1)  ][r] = packh2(va[i].x*ascale, va[i].y*ascale);
            As2[(cc>>1)+1][r] = packh2(va[i].z*ascale, va[i].w*ascale);
        }
        #pragma unroll
        for (int i = 0; i < 2; i++){
            int q = tid + 256*i;
            int row = q >> 5, c4 = q & 31;
            *(uint4*)&Bs2[row][c4*4] = vb[i];
        }
        __syncthreads();
        if (kt + 32 < K){
            #pragma unroll
            for (int i = 0; i < 4; i++){
                int q = tid + 256*i;
                int r = q >> 3, cc = (q & 7) << 2;
                va[i] = *(const float4*)(A + (size_t)(bm + r) * K + kt + 32 + cc);
            }
            #pragma unroll
            for (int i = 0; i < 2; i++){
                int q = tid + 256*i;
                int row = q >> 5, c4 = q & 31;
                vb[i] = *(const uint4*)(Bp + (size_t)((kt >> 1) + 16 + row) * N + bn + c4*4);
            }
        }

        #pragma unroll
        for (int s = 0; s < 2; s++){
            int s8 = s * 8;
            unsigned bf[8][2];
            #pragma unroll
            for (int nt = 0; nt < 8; nt++){
                int col = wn*64 + nt*8 + g;
                bf[nt][0] = Bs2[s8+tg  ][col];
                bf[nt][1] = Bs2[s8+tg+4][col];
            }
            #pragma unroll
            for (int mt = 0; mt < 2; mt++){
                int mb = wm*32 + mt*16;
                unsigned a0 = As2[s8+tg  ][mb+g];
                unsigned a1 = As2[s8+tg  ][mb+8+g];
                unsigned a2 = As2[s8+tg+4][mb+g];
                unsigned a3 = As2[s8+tg+4][mb+8+g];
                #pragma unroll
                for (int nt = 0; nt < 8; nt++){
                    asm volatile(
                        "mma.sync.aligned.m16n8k16.row.col.f32.f16.f16.f32 "
                        "{%0,%1,%2,%3}, {%4,%5,%6,%7}, {%8,%9}, {%0,%1,%2,%3};"
                        : "+f"(c[mt][nt][0]), "+f"(c[mt][nt][1]),
                          "+f"(c[mt][nt][2]), "+f"(c[mt][nt][3])
                        : "r"(a0), "r"(a1), "r"(a2), "r"(a3),
                          "r"(bf[nt][0]), "r"(bf[nt][1]));
                }
            }
        }
        __syncthreads();
    }

    #pragma unroll
    for (int mt = 0; mt < 2; mt++){
        int row0 = bm + wm*32 + mt*16 + g;
        #pragma unroll
        for (int nt = 0; nt < 8; nt++){
            int col = bn + wn*64 + nt*8 + 2*tg;
            float b0 = 0.f, b1 = 0.f;
            if (bias){ b0 = bias[col]; b1 = bias[col+1]; }
            float2 v0, v1;
            v0.x = c[mt][nt][0]*inv_ascale + b0; v0.y = c[mt][nt][1]*inv_ascale + b1;
            v1.x = c[mt][nt][2]*inv_ascale + b0; v1.y = c[mt][nt][3]*inv_ascale + b1;
            if (act){ v0.x = lk(v0.x); v0.y = lk(v0.y); v1.x = lk(v1.x); v1.y = lk(v1.y); }
            if (OUTH){
                __half* C = (__half*)Cv + (size_t)blockIdx.z * sCz;
                *(__half2*)(C + (size_t)row0 * ldc + col)       = __floats2half2_rn(v0.x*oscale, v0.y*oscale);
                *(__half2*)(C + (size_t)(row0 + 8) * ldc + col) = __floats2half2_rn(v1.x*oscale, v1.y*oscale);
            } else {
                float* C = (float*)Cv + (size_t)blockIdx.z * sCz;
                *(float2*)(C + (size_t)row0 * ldc + col)       = v0;
                *(float2*)(C + (size_t)(row0 + 8) * ldc + col) = v1;
            }
        }
    }
}

// ---------------- fp16-input NT GEMM: C = (A[M,K] @ B[N,K]^T) * oscale ----------------
__global__ void __launch_bounds__(256) k_hmma_nt(
    const __half* __restrict__ A, const __half* __restrict__ B,
    float* __restrict__ C, int M, int N, int K, int ldc,
    long long sAz, long long sBz, long long sCz, float oscale)
{
    __shared__ unsigned As2[16][136];
    __shared__ unsigned Bs2[16][136];
    int z = blockIdx.z;
    A += (size_t)z * sAz; B += (size_t)z * sBz; C += (size_t)z * sCz;
    int bm = blockIdx.y * 128, bn = blockIdx.x * 128;
    int tid = threadIdx.x;
    int warp = tid >> 5, lane = tid & 31;
    int wm = warp & 3, wn = warp >> 2;
    int g = lane >> 2, tg = lane & 3;

    float c[2][8][4];
    #pragma unroll
    for (int mt = 0; mt < 2; mt++)
        #pragma unroll
        for (int nt = 0; nt < 8; nt++)
            #pragma unroll
            for (int i = 0; i < 4; i++) c[mt][nt][i] = 0.f;

    float4 va[2], vb[2];
    #pragma unroll
    for (int i = 0; i < 2; i++){
        int q = tid + 256*i;
        int r = q >> 2, cc = (q & 3) << 3;
        va[i] = *(const float4*)(A + (size_t)(bm + r) * K + cc);
        vb[i] = *(const float4*)(B + (size_t)(bn + r) * K + cc);
    }

    for (int kt = 0; kt < K; kt += 32){
        #pragma unroll
        for (int i = 0; i < 2; i++){
            int q = tid + 256*i;
            int r = q >> 2, cc = (q & 3) << 3;
            const unsigned* pa = (const unsigned*)&va[i];
            const unsigned* pb = (const unsigned*)&vb[i];
            int kh = cc >> 1;
            As2[kh  ][r] = pa[0]; As2[kh+1][r] = pa[1];
            As2[kh+2][r] = pa[2]; As2[kh+3][r] = pa[3];
            Bs2[kh  ][r] = pb[0]; Bs2[kh+1][r] = pb[1];
            Bs2[kh+2][r] = pb[2]; Bs2[kh+3][r] = pb[3];
        }
        __syncthreads();
        if (kt + 32 < K){
            #pragma unroll
            for (int i = 0; i < 2; i++){
                int q = tid + 256*i;
                int r = q >> 2, cc = (q & 3) << 3;
                va[i] = *(const float4*)(A + (size_t)(bm + r) * K + kt + 32 + cc);
                vb[i] = *(const float4*)(B + (size_t)(bn + r) * K + kt + 32 + cc);
            }
        }

        #pragma unroll
        for (int s = 0; s < 2; s++){
            int s8 = s * 8;
            unsigned bf[8][2];
            #pragma unroll
            for (int nt = 0; nt < 8; nt++){
                int col = wn*64 + nt*8 + g;
                bf[nt][0] = Bs2[s8+tg  ][col];
                bf[nt][1] = Bs2[s8+tg+4][col];
            }
            #pragma unroll
            for (int mt = 0; mt < 2; mt++){
                int mb = wm*32 + mt*16;
                unsigned a0 = As2[s8+tg  ][mb+g];
                unsigned a1 = As2[s8+tg  ][mb+8+g];
                unsigned a2 = As2[s8+tg+4][mb+g];
                unsigned a3 = As2[s8+tg+4][mb+8+g];
                #pragma unroll
                for (int nt = 0; nt < 8; nt++){
                    asm volatile(
                        "mma.sync.aligned.m16n8k16.row.col.f32.f16.f16.f32 "
                        "{%0,%1,%2,%3}, {%4,%5,%6,%7}, {%8,%9}, {%0,%1,%2,%3};"
                        : "+f"(c[mt][nt][0]), "+f"(c[mt][nt][1]),
                          "+f"(c[mt][nt][2]), "+f"(c[mt][nt][3])
                        : "r"(a0), "r"(a1), "r"(a2), "r"(a3),
                          "r"(bf[nt][0]), "r"(bf[nt][1]));
                }
            }
        }
        __syncthreads();
    }

    #pragma unroll
    for (int mt = 0; mt < 2; mt++){
        int row0 = bm + wm*32 + mt*16 + g;
        #pragma unroll
        for (int nt = 0; nt < 8; nt++){
            int col = bn + wn*64 + nt*8 + 2*tg;
            float2 v0, v1;
            v0.x = c[mt][nt][0]*oscale; v0.y = c[mt][nt][1]*oscale;
            v1.x = c[mt][nt][2]*oscale; v1.y = c[mt][nt][3]*oscale;
            __stcs((float2*)(C + (size_t)row0 * ldc + col), v0);
            __stcs((float2*)(C + (size_t)(row0 + 8) * ldc + col), v1);
        }
    }
}

// ---------------- w1/w2: Wh_l[b] @ att halves (both layers) ----------------
__global__ void k_watt(const float* __restrict__ Wh1, const float* __restrict__ at1,
                       const float* __restrict__ Wh2, const float* __restrict__ at2){
    int w = (blockIdx.x * blockDim.x + threadIdx.x) >> 5;
    int lane = threadIdx.x & 31;
    if (w >= 2*2*3*FF) return;
    int l    = w / (2*3*FF);
    int half = (w / (3*FF)) % 2;
    int b    = (w / FF) % 3, k = w % FF;
    const float* Wh  = l ? Wh2 : Wh1;
    const float* att = l ? at2 : at1;
    const float* row = Wh + (size_t)b*FF*FF + (size_t)k*FF;
    const float* av  = att + b*512 + half*256;
    float4 r0 = ((const float4*)row)[lane*2], r1 = ((const float4*)row)[lane*2+1];
    float4 a0 = ((const float4*)av )[lane*2], a1 = ((const float4*)av )[lane*2+1];
    float s = r0.x*a0.x + r0.y*a0.y + r0.z*a0.z + r0.w*a0.w
            + r1.x*a1.x + r1.y*a1.y + r1.z*a1.z + r1.w*a1.w;
    #pragma unroll
    for (int o = 16; o; o >>= 1) s += __shfl_xor_sync(0xffffffffu, s, o);
    if (lane == 0){
        if (half) g_w2[l][b][k] = s;
        else      g_w1[l][b][k] = s;
    }
}

// ---------------- s2[l][b][e] = hA[e] . w2[l][b] ----------------
__global__ void k_s2all(const float* __restrict__ hA){
    int w = (blockIdx.x * blockDim.x + threadIdx.x) >> 5;
    int lane = threadIdx.x & 31;
    if (w >= MM) return;
    int e = w;
    const float* row = hA + (size_t)e*FF;
    float4 r0 = ((const float4*)row)[lane*2], r1 = ((const float4*)row)[lane*2+1];
    #pragma unroll
    for (int q = 0; q < 6; q++){
        const float* w2 = g_w2[q/3][q%3];
        float4 a0 = ((const float4*)w2)[lane*2], a1 = ((const float4*)w2)[lane*2+1];
        float s = r0.x*a0.x + r0.y*a0.y + r0.z*a0.z + r0.w*a0.w
                + r1.x*a1.x + r1.y*a1.y + r1.z*a1.z + r1.w*a1.w;
        #pragma unroll
        for (int o = 16; o; o >>= 1) s += __shfl_xor_sync(0xffffffffu, s, o);
        if (lane == 0) g_s2[q/3][q%3][e] = s;
    }
}

// ---------------- s1[b][n] = h[n] . w1[l][b] ----------------
__global__ void k_s1(int l, const float* __restrict__ hsrc){
    int w = (blockIdx.x * blockDim.x + threadIdx.x) >> 5;
    int lane = threadIdx.x & 31;
    if (w >= NN) return;
    int n = w;
    const float4* hr = (const float4*)(hsrc + (size_t)n*FF);
    float4 v0 = hr[lane], v1 = hr[32+lane];
    #pragma unroll
    for (int b = 0; b < 3; b++){
        const float* w1 = g_w1[l][b];
        float4 a0 = ((const float4*)w1)[lane], a1 = ((const float4*)w1)[32+lane];
        float s = v0.x*a0.x + v0.y*a0.y + v0.z*a0.z + v0.w*a0.w
                + v1.x*a1.x + v1.y*a1.y + v1.z*a1.z + v1.w*a1.w;
        #pragma unroll
        for (int o = 16; o; o >>= 1) s += __shfl_xor_sync(0xffffffffu, s, o);
        if (lane == 0) g_s1[b][n] = s;
    }
}

// ---------------- stats: single-pass online softmax (+ D on layer 0) -> ninfo ----------------
__global__ void k_stats(int l, const float* __restrict__ hw, int computeD){
    int w = (blockIdx.x * blockDim.x + threadIdx.x) >> 5;
    int lane = threadIdx.x & 31;
    if (w >= 3*NN) return;
    int b = w / NN, n = w % NN;

    float s1n = g_s1[b][n];
    const float* s2b = g_s2[l][b];
    int beg = g_noff[b][n], end = g_noff[b][n+1];

    float mx = -1e30f, sum = 0.f, ds = 0.f;
    for (int p = beg + lane; p < end; p += 32){
        int e = __ldcs(&g_eiN[b][p]);
        float a = lk(s1n + s2b[e]);
        if (computeD) ds += hw[e];
        float mo = mx;
        mx = fmaxf(mx, a);
        sum = sum * __expf(mo - mx) + __expf(a - mx);
    }
    #pragma unroll
    for (int o = 16; o; o >>= 1){
        float mo2 = __shfl_xor_sync(0xffffffffu, mx, o);
        float so2 = __shfl_xor_sync(0xffffffffu, sum, o);
        float mn = fmaxf(mx, mo2);
        sum = sum * __expf(mx - mn) + so2 * __expf(mo2 - mn);
        mx = mn;
        if (computeD) ds += __shfl_xor_sync(0xffffffffu, ds, o);
    }
    if (lane == 0){
        float di;
        if (computeD){
            di = (ds > 0.f) ? 1.f/ds : 0.f;
            g_Dv[b][n] = di;
        } else {
            di = g_Dv[b][n];
        }
        if (end > beg) g_ninfo[b][n] = make_float4(s1n, mx, 1.f/sum, di);
        else           g_ninfo[b][n] = make_float4(s1n, 0.f, 0.f, 0.f);
    }
}

// ---------------- gather helper: accumulate one row into acc[8] ----------------
__device__ __forceinline__ void row_acc(const __half* base, int r, int lane, float c, float* acc){
    float4 raw = *(const float4*)(base + (size_t)r * FF + lane*8);
    const __half2* hp = (const __half2*)&raw;
    #pragma unroll
    for (int q = 0; q < 4; q++){
        float2 f = __half22float2(hp[q]);
        acc[2*q]   += c*f.x;
        acc[2*q+1] += c*f.y;
    }
}

// ---------------- edge pass: 4-way unrolled gather ----------------
__global__ void k_edge(int l){
    int w = (blockIdx.x * blockDim.x + threadIdx.x) >> 5;
    int lane = threadIdx.x & 31;
    if (w >= 3*MM) return;
    int b = w / MM, e = w % MM;
    int beg = g_eoff[b][e], end = g_eoff[b][e+1];
    float s2e = g_s2[l][b][e];
    const __half* xlb = g_xl[b];
    float acc[8] = {0,0,0,0,0,0,0,0};
    for (int base = beg; base < end; base += 32){
        int p = base + lane;
        int nrow = 0; float coef = 0.f;
        if (p < end){
            nrow = __ldcs(&g_niE[b][p]);
            float4 info = g_ninfo[b][nrow];
            coef = __expf(lk(info.x + s2e) - info.y) * info.z;
        }
        int cnt = min(32, end - base);
        int t = 0;
        for (; t + 4 <= cnt; t += 4){
            int   r0 = __shfl_sync(0xffffffffu, nrow, t);
            float c0 = __shfl_sync(0xffffffffu, coef, t);
            int   r1 = __shfl_sync(0xffffffffu, nrow, t+1);
            float c1 = __shfl_sync(0xffffffffu, coef, t+1);
            int   r2 = __shfl_sync(0xffffffffu, nrow, t+2);
            float c2 = __shfl_sync(0xffffffffu, coef, t+2);
            int   r3 = __shfl_sync(0xffffffffu, nrow, t+3);
            float c3 = __shfl_sync(0xffffffffu, coef, t+3);
            float4 raw0 = *(const float4*)(xlb + (size_t)r0 * FF + lane*8);
            float4 raw1 = *(const float4*)(xlb + (size_t)r1 * FF + lane*8);
            float4 raw2 = *(const float4*)(xlb + (size_t)r2 * FF + lane*8);
            float4 raw3 = *(const float4*)(xlb + (size_t)r3 * FF + lane*8);
            const __half2* h0 = (const __half2*)&raw0;
            const __half2* h1 = (const __half2*)&raw1;
            const __half2* h2 = (const __half2*)&raw2;
            const __half2* h3 = (const __half2*)&raw3;
            #pragma unroll
            for (int q = 0; q < 4; q++){
                float2 f0 = __half22float2(h0[q]);
                float2 f1 = __half22float2(h1[q]);
                float2 f2 = __half22float2(h2[q]);
                float2 f3 = __half22float2(h3[q]);
                acc[2*q]   += c0*f0.x + c1*f1.x + c2*f2.x + c3*f3.x;
                acc[2*q+1] += c0*f0.y + c1*f1.y + c2*f2.y + c3*f3.y;
            }
        }
        for (; t < cnt; t++){
            int   r0 = __shfl_sync(0xffffffffu, nrow, t);
            float c0 = __shfl_sync(0xffffffffu, coef, t);
            row_acc(xlb, r0, lane, c0, acc);
        }
    }
    int ce = end - beg;
    float bi = (ce > 0) ? 1.f/(float)ce : 0.f;
    __half2 o[4];
    o[0] = __floats2half2_rn(bi*acc[0], bi*acc[1]);
    o[1] = __floats2half2_rn(bi*acc[2], bi*acc[3]);
    o[2] = __floats2half2_rn(bi*acc[4], bi*acc[5]);
    o[3] = __floats2half2_rn(bi*acc[6], bi*acc[7]);
    *(float4*)(g_m[b] + (size_t)e * FF + lane*8) = *(float4*)o;
}

// ---------------- node pass: 4-way unrolled, node range [n0, n0+ncount) ----------------
__global__ void k_node(int l, const float* __restrict__ bc, float* __restrict__ hout,
                       float invS, int n0, int ncount){
    int w = (blockIdx.x * blockDim.x + threadIdx.x) >> 5;
    int lane = threadIdx.x & 31;
    if (w >= ncount) return;
    int n = n0 + w;
    float t[8] = {0,0,0,0,0,0,0,0};
    #pragma unroll
    for (int b = 0; b < 3; b++){
        int beg = g_noff[b][n], end = g_noff[b][n+1];
        float4 info = g_ninfo[b][n];
        float s1n = info.x, mxn = info.y, rsn = info.z, di = info.w;
        const float* s2b = g_s2[l][b];
        const __half* mb = g_m[b];
        float a[8] = {0,0,0,0,0,0,0,0};
        for (int base = beg; base < end; base += 32){
            int p = base + lane;
            int er = 0; float coef = 0.f;
            if (p < end){
                er = __ldcs(&g_eiN[b][p]);
                coef = __expf(lk(s1n + s2b[er]) - mxn) * rsn;
            }
            int cnt = min(32, end - base);
            int t2 = 0;
            for (; t2 + 4 <= cnt; t2 += 4){
                int   r0 = __shfl_sync(0xffffffffu, er, t2);
                float c0 = __shfl_sync(0xffffffffu, coef, t2);
                int   r1 = __shfl_sync(0xffffffffu, er, t2+1);
                float c1 = __shfl_sync(0xffffffffu, coef, t2+1);
                int   r2 = __shfl_sync(0xffffffffu, er, t2+2);
                float c2 = __shfl_sync(0xffffffffu, coef, t2+2);
                int   r3 = __shfl_sync(0xffffffffu, er, t2+3);
                float c3 = __shfl_sync(0xffffffffu, coef, t2+3);
                float4 raw0 = *(const float4*)(mb + (size_t)r0 * FF + lane*8);
                float4 raw1 = *(const float4*)(mb + (size_t)r1 * FF + lane*8);
                float4 raw2 = *(const float4*)(mb + (size_t)r2 * FF + lane*8);
                float4 raw3 = *(const float4*)(mb + (size_t)r3 * FF + lane*8);
                const __half2* h0 = (const __half2*)&raw0;
                const __half2* h1 = (const __half2*)&raw1;
                const __half2* h2 = (const __half2*)&raw2;
                const __half2* h3 = (const __half2*)&raw3;
                #pragma unroll
                for (int q = 0; q < 4; q++){
                    float2 f0 = __half22float2(h0[q]);
                    float2 f1 = __half22float2(h1[q]);
                    float2 f2 = __half22float2(h2[q]);
                    float2 f3 = __half22float2(h3[q]);
                    a[2*q]   += c0*f0.x + c1*f1.x + c2*f2.x + c3*f3.x;
                    a[2*q+1] += c0*f0.y + c1*f1.y + c2*f2.y + c3*f3.y;
                }
            }
            for (; t2 < cnt; t2++){
                int   r0 = __shfl_sync(0xffffffffu, er, t2);
                float c0 = __shfl_sync(0xffffffffu, coef, t2);
                row_acc(mb, r0, lane, c0, a);
            }
        }
        #pragma unroll
        for (int i = 0; i < 8; i++) t[i] += di * a[i];
    }
    #pragma unroll
    for (int i = 0; i < 8; i++) t[i] *= invS;
    #pragma unroll
    for (int k = 0; k < 3; k++){
        float4 b0 = *(const float4*)(bc + k*256 + lane*8);
        float4 b1 = *(const float4*)(bc + k*256 + lane*8 + 4);
        t[0] += b0.x; t[1] += b0.y; t[2] += b0.z; t[3] += b0.w;
        t[4] += b1.x; t[5] += b1.y; t[6] += b1.z; t[7] += b1.w;
    }
    #pragma unroll
    for (int i = 0; i < 8; i++) t[i] = lk(t[i]);
    *(float4*)(hout + (size_t)n * FF + lane*8)     = make_float4(t[0], t[1], t[2], t[3]);
    *(float4*)(hout + (size_t)n * FF + lane*8 + 4) = make_float4(t[4], t[5], t[6], t[7]);
}

// ---------------- host launcher ----------------
static void* symaddr(const void* sym){ void* p = nullptr; cudaGetSymbolAddress(&p, sym); return p; }

extern "C" void kernel_launch(void* const* d_in, const int* in_sizes, int n_in,
                              void* d_out, int out_size){
    const float* g   = (const float*)d_in[0];
    const float* x   = (const float*)d_in[1];
    const float* hw  = (const float*)d_in[2];
    const float* hA  = (const float*)d_in[3];
    const int* ni0 = (const int*)d_in[4]; const int* ei0 = (const int*)d_in[5];
    const int* ni1 = (const int*)d_in[6]; const int* ei1 = (const int*)d_in[7];
    const int* ni2 = (const int*)d_in[8]; const int* ei2 = (const int*)d_in[9];
    const float* W0  = (const float*)d_in[10]; const float* b0  = (const float*)d_in[11];
    const float* Wh1 = (const float*)d_in[12]; const float* at1 = (const float*)d_in[13];
    const float* bc1 = (const float*)d_in[14];
    const float* W1  = (const float*)d_in[15]; const float* b1  = (const float*)d_in[16];
    const float* Wh2 = (const float*)d_in[17]; const float* at2 = (const float*)d_in[18];
    const float* bc2 = (const float*)d_in[19];
    const float* Wg  = (const float*)d_in[20]; const float* bg  = (const float*)d_in[21];
    const float* Wx  = (const float*)d_in[22]; const float* bx  = (const float*)d_in[23];
    float* out = (float*)d_out;

    float*    p_h     = (float*)symaddr(g_h);
    float*    p_h2    = (float*)symaddr(g_h2);
    void*     p_xl    = symaddr(g_xl);
    void*     p_newgh = symaddr(g_newgh);
    void*     p_xsh   = symaddr(g_xsh);
    const unsigned* pWp  = (const unsigned*)symaddr(g_Wp);
    const unsigned* pWpc = (const unsigned*)symaddr(g_Wpc);

    const float S1 = 1.f,    IS1 = 1.f;
    const float SK = 1024.f, ISK = 1.f/1024.f;

    cudaStream_t sB = 0;
    cudaEvent_t evF = 0, evJ = 0, evL1 = 0, evS1 = 0, evE = 0, evN0 = 0;
    cudaStreamCreateWithFlags(&sB, cudaStreamNonBlocking);
    cudaEventCreateWithFlags(&evF,  cudaEventDisableTiming);
    cudaEventCreateWithFlags(&evJ,  cudaEventDisableTiming);
    cudaEventCreateWithFlags(&evL1, cudaEventDisableTiming);
    cudaEventCreateWithFlags(&evS1, cudaEventDisableTiming);
    cudaEventCreateWithFlags(&evE,  cudaEventDisableTiming);
    cudaEventCreateWithFlags(&evN0, cudaEventDisableTiming);

    cudaEventRecord(evF, 0);
    cudaStreamWaitEvent(sB, evF, 0);

    // ---- side stream: CSR build ----
    k_zero<<<(3*(MM+1) + 255)/256, 256, 0, sB>>>();
    k_hist<<<(3*EE + 255)/256, 256, 0, sB>>>(ni0, ei0, ni1, ei1, ni2, ei2);
    k_scan<<<6, 1024, 0, sB>>>();
    k_scatter<<<(3*EE + 255)/256, 256, 0, sB>>>(ni0, ei0, ni1, ei1, ni2, ei2);
    cudaEventRecord(evJ, sB);

    // ---- main: weight prep, layer0, hyper1-lin, attention precompute, xs, s1(0) ----
    k_prepw<<<(4*3*32768 + 2*2*16384 + 255)/256, 256>>>(W0, Wh1, W1, Wh2, Wg, Wx);
    k_hmma<0><<<dim3(2,32,3), 256>>>(g, pWp + 0*98304, p_h, b0, 4096, 256, 256, 256,
                                     (long long)4096*256, 32768LL, (long long)4096*256, 256LL, 1, S1, IS1, 1.f);
    k_hmma<1><<<dim3(2,96,3), 256>>>(p_h, pWp + 1*98304, p_xl, nullptr, 12288, 256, 256, 256,
                                     0LL, 32768LL, (long long)12288*256, 0LL, 0, S1, IS1, 1.f);
    k_watt<<<(2*2*3*FF*32 + 255)/256, 256>>>(Wh1, at1, Wh2, at2);
    k_s2all<<<(MM*32 + 255)/256, 256>>>(hA);
    k_hmma<1><<<dim3(1,32,2), 256>>>(x, pWpc + 32768, p_xsh, bx + 128,
                                     4096, 128, 256, 128,
                                     0LL, 16384LL, (long long)4096*128, 128LL, 1, S1, IS1, 1.f);
    k_s1<<<(NN*32 + 255)/256, 256>>>(0, p_h);
    cudaStreamWaitEvent(0, evJ, 0);

    // ---- hyper1 ----
    k_stats<<<(3*NN*32 + 255)/256, 256>>>(0, hw, 1);
    k_edge<<<(3*MM*32 + 255)/256, 256>>>(0);
    k_node<<<(NN*32 + 255)/256, 256>>>(0, bc1, p_h, IS1, 0, NN);

    // ---- layer1 ----
    k_hmma<0><<<dim3(2,32,3), 256>>>(p_h, pWp + 2*98304, p_h2, b1, 4096, 256, 256, 256,
                                     (long long)4096*256, 32768LL, (long long)4096*256, 256LL, 1, SK, ISK, 1.f);
    cudaEventRecord(evL1, 0);

    // ---- side stream: s1(1) overlapped with hyper2-lin GEMM ----
    cudaStreamWaitEvent(sB, evL1, 0);
    k_s1<<<(NN*32 + 255)/256, 256, 0, sB>>>(1, p_h2);
    cudaEventRecord(evS1, sB);

    // ---- hyper2 ----
    k_hmma<1><<<dim3(2,96,3), 256>>>(p_h2, pWp + 3*98304, p_xl, nullptr, 12288, 256, 256, 256,
                                     0LL, 32768LL, (long long)12288*256, 0LL, 0, SK, ISK, 1024.f);
    cudaStreamWaitEvent(0, evS1, 0);
    k_stats<<<(3*NN*32 + 255)/256, 256>>>(1, hw, 0);
    k_edge<<<(3*MM*32 + 255)/256, 256>>>(1);
    cudaEventRecord(evE, 0);

    // side stream: node segment 0 (rows 0..4095) — pure output, off critical path
    cudaStreamWaitEvent(sB, evE, 0);
    k_node<<<(4096*32 + 255)/256, 256, 0, sB>>>(1, bc2, out + HOFF, ISK, 0, 4096);
    cudaEventRecord(evN0, sB);

    // main: node segments 1-2 (rows 4096..12288) — feeds the projection
    k_node<<<(8192*32 + 255)/256, 256>>>(1, bc2, out + HOFF, ISK, 4096, 8192);

    // ---- new_g projection (reads only rows 4096..12288 of h) ----
    k_hmma<1><<<dim3(1,32,2), 256>>>(out + HOFF + (size_t)4096*256, pWpc + 0, p_newgh, bg + 128,
                                     4096, 128, 256, 128,
                                     (long long)4096*256, 16384LL, (long long)4096*128, 128LL, 1, SK, ISK, 1024.f);

    // ---- result ----
    k_hmma_nt<<<dim3(32,32,2), 256>>>((const __half*)p_xsh, (const __half*)p_newgh, out,
                                      4096, 4096, 128, 8192,
                                      (long long)4096*128, (long long)4096*128, 4096LL, ISK);

    // join side stream before capture end
    cudaStreamWaitEvent(0, evN0, 0);
}